// round 2
// baseline (speedup 1.0000x reference)
#include <cuda_runtime.h>
#include <math.h>

#define SEQN 2048
#define NAMP 256
#define PF 8

// ---- device scratch (no allocations allowed) ----
__device__ float g_trig[2 * 63];      // cos,sin of w[j]/2
__device__ float g_q[SEQN];           // QCNN outputs <Z_7> per sample
__device__ int   g_flag[SEQN];        // per-sample ready flags (zeroed by prep each call)
__device__ float g_hs[SEQN * 4];      // LSTM hidden states
__device__ float g_tanhpoly[6];       // runtime-fitted odd poly for tanh on [-1,1]

// ---- acquire/release helpers ----
__device__ __forceinline__ int ld_acq(const int* p) {
    int v;
    asm volatile("ld.acquire.gpu.global.b32 %0, [%1];" : "=r"(v) : "l"(p) : "memory");
    return v;
}
__device__ __forceinline__ void st_rel(int* p, int v) {
    asm volatile("st.release.gpu.global.b32 [%0], %1;" :: "l"(p), "r"(v) : "memory");
}

// ============================================================
// Kernel 1: trig precompute + flag zeroing + runtime poly fit.
// Fits tanh(z) ~= z * P(z^2) on [-1,1] (deg-11 odd) by Chebyshev-node
// interpolation of g(u)=tanh(sqrt(u))/sqrt(u) on u in [0,1], solved in
// double precision (6x6 Gauss with partial pivoting).
// ============================================================
__global__ void prep_kernel(const float* __restrict__ w) {
    int j = threadIdx.x;
    if (j < 63) {
        float s, c;
        sincosf(0.5f * w[j], &s, &c);
        g_trig[2 * j]     = c;
        g_trig[2 * j + 1] = s;
    }
    for (int i = j; i < SEQN; i += blockDim.x) g_flag[i] = 0;

    if (j == 0) {
        double U[6], Gv[6], a[6];
        for (int k = 0; k < 6; k++) {
            double th = (2.0 * k + 1.0) * 3.14159265358979323846 / 12.0;
            double u  = 0.5 * (1.0 + cos(th));
            double s  = sqrt(u);
            U[k] = u; Gv[k] = tanh(s) / s;
        }
        double M[6][7];
        for (int r = 0; r < 6; r++) {
            double p = 1.0;
            for (int c = 0; c < 6; c++) { M[r][c] = p; p *= U[r]; }
            M[r][6] = Gv[r];
        }
        for (int k = 0; k < 6; k++) {
            int piv = k;
            for (int i = k + 1; i < 6; i++)
                if (fabs(M[i][k]) > fabs(M[piv][k])) piv = i;
            if (piv != k)
                for (int c = 0; c < 7; c++) { double t = M[k][c]; M[k][c] = M[piv][c]; M[piv][c] = t; }
            for (int i = k + 1; i < 6; i++) {
                double f = M[i][k] / M[k][k];
                for (int c = k; c < 7; c++) M[i][c] -= f * M[k][c];
            }
        }
        for (int k = 5; k >= 0; k--) {
            double v = M[k][6];
            for (int c = k + 1; c < 6; c++) v -= M[k][c] * a[c];
            a[k] = v / M[k][k];
        }
        for (int k = 0; k < 6; k++) g_tanhpoly[k] = (float)a[k];
    }
}

// ============================================================
// QCNN sample simulation (device fn; one block of 256 threads).
// ============================================================
__device__ void qcnn_sample(const float* __restrict__ sentence, int s) {
    __shared__ float2 buf[2][NAMP];
    __shared__ float tc[63], ts[63];
    __shared__ float xc[8], xs[8];
    __shared__ float red[8];

    const int tid = threadIdx.x;

    if (tid < 63) { tc[tid] = g_trig[2 * tid]; ts[tid] = g_trig[2 * tid + 1]; }
    if (tid >= 64 && tid < 72) {
        int q = tid - 64;
        float x = sentence[s * 8 + q];
        float sn, cs;
        sincosf(2.0f * x, &sn, &cs);
        xc[q] = cs; xs[q] = sn;
    }
    __syncthreads();

    float re = (tid == 0) ? 1.0f : 0.0f;
    float im = 0.0f;
    int pb = 0;
    const float RT = 0.70710678118654752440f;

    auto H = [&](int q) {
        buf[pb][tid] = make_float2(re, im);
        __syncthreads();
        float2 o = buf[pb][tid ^ (1 << q)];
        pb ^= 1;
        if ((tid >> q) & 1) { re = (o.x - re) * RT; im = (o.y - im) * RT; }
        else                { re = (re + o.x) * RT; im = (im + o.y) * RT; }
    };
    auto PH = [&](int q, float c, float sn) {
        if ((tid >> q) & 1) {
            float nr = re * c - im * sn;
            im = re * sn + im * c;
            re = nr;
        }
    };
    auto RZ = [&](int q, float c, float sn) {
        float ss = ((tid >> q) & 1) ? sn : -sn;
        float nr = re * c - im * ss;
        im = re * ss + im * c;
        re = nr;
    };
    auto RY = [&](int q, float c, float sn) {
        buf[pb][tid] = make_float2(re, im);
        __syncthreads();
        float2 o = buf[pb][tid ^ (1 << q)];
        pb ^= 1;
        float ss = ((tid >> q) & 1) ? sn : -sn;
        re = c * re + ss * o.x;
        im = c * im + ss * o.y;
    };
    auto CNOT = [&](int cq, int tq) {
        buf[pb][tid] = make_float2(re, im);
        __syncthreads();
        int src = ((tid >> cq) & 1) ? (tid ^ (1 << tq)) : tid;
        float2 o = buf[pb][src];
        pb ^= 1;
        re = o.x; im = o.y;
    };
    auto conv = [&](int a, int b, int k) {
        RZ(b, RT, -RT);
        CNOT(b, a);
        RZ(a, tc[k], ts[k]);
        RY(b, tc[k + 1], ts[k + 1]);
        CNOT(a, b);
        RY(b, tc[k + 2], ts[k + 2]);
        CNOT(b, a);
        RZ(a, RT, RT);
    };
    auto pool = [&](int a, int b, int k) {
        RZ(b, RT, -RT);
        CNOT(b, a);
        RZ(a, tc[k], ts[k]);
        RY(b, tc[k + 1], ts[k + 1]);
        CNOT(a, b);
        RY(b, tc[k + 2], ts[k + 2]);
    };

#pragma unroll
    for (int q = 0; q < 8; q++) { H(q); PH(q, xc[q], xs[q]); }

    int k = 0;
    conv(0, 1, k); k += 3;  conv(2, 3, k); k += 3;
    conv(4, 5, k); k += 3;  conv(6, 7, k); k += 3;
    conv(1, 2, k); k += 3;  conv(3, 4, k); k += 3;
    conv(5, 6, k); k += 3;  conv(7, 0, k); k += 3;
    pool(0, 4, k); k += 3;  pool(1, 5, k); k += 3;
    pool(2, 6, k); k += 3;  pool(3, 7, k); k += 3;
    conv(0, 1, k); k += 3;  conv(2, 3, k); k += 3;
    conv(1, 2, k); k += 3;  conv(3, 0, k); k += 3;
    pool(0, 2, k); k += 3;  pool(1, 3, k); k += 3;
    conv(0, 1, k); k += 3;  conv(1, 0, k); k += 3;
    pool(0, 1, k); k += 3;

    float p = re * re + im * im;
    float v = (tid & 128) ? -p : p;
#pragma unroll
    for (int o = 16; o; o >>= 1) v += __shfl_xor_sync(0xFFFFFFFFu, v, o);
    if ((tid & 31) == 0) red[tid >> 5] = v;
    __syncthreads();
    if (tid == 0) {
        float sv = 0.0f;
#pragma unroll
        for (int i = 0; i < 8; i++) sv += red[i];
        g_q[s] = sv;
        st_rel(&g_flag[s], 1);   // release: q visible before flag
    }
}

// ============================================================
// QLSTM sequential scan (device fn; warp 0 of block 0, 16 lanes).
// Quantum layer collapsed analytically to cosine products:
//   z0=c1c2c3, z1=c0c1, z2=c0c1c2, z3=c0c1c2c3
// Activations of z via pure-FMA odd polynomials (z in [-1,1]).
// tanh(c) via exact EX2+RCP path.
// ============================================================
__device__ void qlstm_scan(const float* __restrict__ Wf, const float* __restrict__ bf,
                           const float* __restrict__ Wi, const float* __restrict__ bi,
                           const float* __restrict__ Wu, const float* __restrict__ bu,
                           const float* __restrict__ Wo, const float* __restrict__ bo,
                           const float* __restrict__ thf, const float* __restrict__ thi,
                           const float* __restrict__ thu, const float* __restrict__ tho) {
    const int l = threadIdx.x;
    if (l >= 16) return;

    const int g = l >> 2;
    const int q = l & 3;
    const int base = l & ~3;
    const unsigned M = 0x0000FFFFu;

    const float* W  = (g == 0) ? Wf  : (g == 1) ? Wi  : (g == 2) ? Wu  : Wo;
    const float* b  = (g == 0) ? bf  : (g == 1) ? bi  : (g == 2) ? bu  : bo;
    const float* th = (g == 0) ? thf : (g == 1) ? thi : (g == 2) ? thu : tho;

    const float W0 = W[q * 5 + 0];
    const float w1 = W[q * 5 + 1], w2 = W[q * 5 + 2];
    const float w3 = W[q * 5 + 3], w4 = W[q * 5 + 4];
    const float ub = b[q] + th[q];

    const bool use0 = (q != 0);
    const bool use2 = (q != 1);
    const bool use3 = (q == 0) || (q == 3);

    // activation poly coefficients: sigmoid lanes = exact Taylor of
    // 0.5 + 0.5*tanh(z/2); u-lane = runtime-fitted tanh poly.
    const bool isU = (g == 2);
    const float k0 = isU ? g_tanhpoly[0] :  0.25f;
    const float k1 = isU ? g_tanhpoly[1] : -2.08333333e-2f;
    const float k2 = isU ? g_tanhpoly[2] :  2.08333333e-3f;
    const float k3 = isU ? g_tanhpoly[3] : -2.10813492e-4f;
    const float k4 = isU ? g_tanhpoly[4] :  2.13569224e-5f;
    const float k5 = isU ? g_tanhpoly[5] : -2.16387000e-6f;
    const float K  = isU ? 0.0f : 0.5f;

    // prefetch queue (register-resident, full unroll keeps indices static)
    float qq[PF];
    int   fq[PF];
#pragma unroll
    for (int j = 0; j < PF; j++) {
        while (ld_acq(&g_flag[j]) == 0) { }
        qq[j] = g_q[j];
        fq[j] = 1;
    }

    float c = 0.0f, h0 = 0.0f, h1 = 0.0f, h2 = 0.0f, h3 = 0.0f;

    for (int t0 = 0; t0 < SEQN; t0 += PF) {
#pragma unroll
        for (int j = 0; j < PF; j++) {
            const int t = t0 + j;
            float qv = qq[j];
            if (fq[j] == 0) {               // rare: producer behind
                while (ld_acq(&g_flag[t]) == 0) { }
                qv = g_q[t];
            }
            // prefetch slot t+PF (flag may legitimately be 0 -> checked at use)
            const int tn = t + PF;
            if (tn < SEQN) {
                fq[j] = ld_acq(&g_flag[tn]);
                qq[j] = g_q[tn];
            } else {
                fq[j] = 1; qq[j] = 0.0f;
            }

            const float bse = fmaf(W0, qv, ub);
            float A = fmaf(w1, h0, bse);
            A = fmaf(w2, h1, A);
            float B = w4 * h3;
            B = fmaf(w3, h2, B);
            const float y = A + B;

            const float cz = __cosf(y);

            const float c0 = __shfl_sync(M, cz, base + 0);
            const float c1 = __shfl_sync(M, cz, base + 1);
            const float c2 = __shfl_sync(M, cz, base + 2);
            const float c3 = __shfl_sync(M, cz, base + 3);

            const float m0 = use0 ? c0 : 1.0f;
            const float m2 = use2 ? c2 : 1.0f;
            const float m3 = use3 ? c3 : 1.0f;
            const float z  = (c1 * m0) * (m2 * m3);

            const float u = z * z;
            float p = fmaf(k5, u, k4);
            p = fmaf(p, u, k3);
            p = fmaf(p, u, k2);
            p = fmaf(p, u, k1);
            p = fmaf(p, u, k0);
            const float act = fmaf(z, p, K);

            const float af = __shfl_sync(M, act, q);
            const float ai = __shfl_sync(M, act, 4 + q);
            const float au = __shfl_sync(M, act, 8 + q);
            const float ao = __shfl_sync(M, act, 12 + q);

            const float aot = ao + ao;
            const float nao = -ao;
            const float gi  = ai * au;
            c = fmaf(af, c, gi);

            // h = ao * tanh(c) = 2*ao*sigmoid(2c) - ao  (exact EX2+RCP path)
            const float e  = __expf(-2.0f * c);
            const float r  = __fdividef(1.0f, 1.0f + e);
            const float hq = fmaf(aot, r, nao);

            if (g == 0) g_hs[t * 4 + q] = hq;

            h0 = __shfl_sync(M, hq, base + 0);
            h1 = __shfl_sync(M, hq, base + 1);
            h2 = __shfl_sync(M, hq, base + 2);
            h3 = __shfl_sync(M, hq, base + 3);
        }
    }
}

// ============================================================
// Kernel 2 (fused): block 0 = qlstm scan (polls flags),
// blocks 1..SEQN = qcnn samples (write q + release flag).
// ============================================================
__global__ void __launch_bounds__(NAMP, 1)
fused_kernel(const float* __restrict__ sentence,
             const float* __restrict__ Wf, const float* __restrict__ bf,
             const float* __restrict__ Wi, const float* __restrict__ bi,
             const float* __restrict__ Wu, const float* __restrict__ bu,
             const float* __restrict__ Wo, const float* __restrict__ bo,
             const float* __restrict__ thf, const float* __restrict__ thi,
             const float* __restrict__ thu, const float* __restrict__ tho) {
    if (blockIdx.x == 0) {
        qlstm_scan(Wf, bf, Wi, bi, Wu, bu, Wo, bo, thf, thi, thu, tho);
    } else {
        qcnn_sample(sentence, blockIdx.x - 1);
    }
}

// ============================================================
// Kernel 3: logits + log_softmax. One warp per timestep row.
// ============================================================
__global__ void head_kernel(const float* __restrict__ Wt, const float* __restrict__ bt,
                            float* __restrict__ out) {
    const int warp = (blockIdx.x * blockDim.x + threadIdx.x) >> 5;
    const int lane = threadIdx.x & 31;
    if (warp >= SEQN) return;

    float h0 = g_hs[warp * 4 + 0];
    float h1 = g_hs[warp * 4 + 1];
    float h2 = g_hs[warp * 4 + 2];
    float h3 = g_hs[warp * 4 + 3];

    float l = bt[lane];
    l = fmaf(h0, Wt[lane * 4 + 0], l);
    l = fmaf(h1, Wt[lane * 4 + 1], l);
    l = fmaf(h2, Wt[lane * 4 + 2], l);
    l = fmaf(h3, Wt[lane * 4 + 3], l);

    float m = l;
#pragma unroll
    for (int o = 16; o; o >>= 1) m = fmaxf(m, __shfl_xor_sync(0xFFFFFFFFu, m, o));
    float e = __expf(l - m);
    float sum = e;
#pragma unroll
    for (int o = 16; o; o >>= 1) sum += __shfl_xor_sync(0xFFFFFFFFu, sum, o);

    out[warp * 32 + lane] = (l - m) - __logf(sum);
}

// ============================================================
extern "C" void kernel_launch(void* const* d_in, const int* in_sizes, int n_in,
                              void* d_out, int out_size) {
    const float* sentence = (const float*)d_in[0];
    const float* qcnn_w   = (const float*)d_in[1];
    const float* Wf  = (const float*)d_in[2];
    const float* bf  = (const float*)d_in[3];
    const float* Wi  = (const float*)d_in[4];
    const float* bi  = (const float*)d_in[5];
    const float* Wu  = (const float*)d_in[6];
    const float* bu  = (const float*)d_in[7];
    const float* Wo  = (const float*)d_in[8];
    const float* bo  = (const float*)d_in[9];
    const float* thf = (const float*)d_in[10];
    const float* thi = (const float*)d_in[11];
    const float* thu = (const float*)d_in[12];
    const float* tho = (const float*)d_in[13];
    const float* Wt  = (const float*)d_in[14];
    const float* bt  = (const float*)d_in[15];
    float* out = (float*)d_out;

    prep_kernel<<<1, 256>>>(qcnn_w);
    fused_kernel<<<SEQN + 1, NAMP>>>(sentence,
                                     Wf, bf, Wi, bi, Wu, bu, Wo, bo,
                                     thf, thi, thu, tho);
    head_kernel<<<(SEQN * 32) / 256, 256>>>(Wt, bt, out);
}

// round 3
// speedup vs baseline: 2.2945x; 2.2945x over previous
#include <cuda_runtime.h>
#include <math.h>

#define SEQN 2048
#define NAMP 256
#define PF 8
#define NBLK 148          // exactly #SMs: block 0 = scan (own SM), 1..147 = producers

#define NOT_READY -1.0e30f
#define QBIAS 10.0f

// ---- device scratch (no allocations allowed) ----
__device__ float g_trig[2 * 63];          // cos,sin of w[j]/2
__device__ volatile float g_q[SEQN];      // sentinel/value channel: ready iff > 5
__device__ float g_hs[SEQN * 4];          // LSTM hidden states

__device__ __forceinline__ float ex2f(float x) {
    float y; asm("ex2.approx.f32 %0, %1;" : "=f"(y) : "f"(x)); return y;
}
__device__ __forceinline__ float rcpf(float x) {
    float y; asm("rcp.approx.f32 %0, %1;" : "=f"(y) : "f"(x)); return y;
}

// ============================================================
// Kernel 1: trig precompute + q-channel sentinel init
// ============================================================
__global__ void prep_kernel(const float* __restrict__ w) {
    int j = threadIdx.x;
    if (j < 63) {
        float s, c;
        sincosf(0.5f * w[j], &s, &c);
        g_trig[2 * j]     = c;
        g_trig[2 * j + 1] = s;
    }
    for (int i = j; i < SEQN; i += blockDim.x) g_q[i] = NOT_READY;
}

// ============================================================
// QCNN producer: persistent block handles samples s0, s0+147, ...
// 256 threads; thread tid owns amplitude tid of the 8-qubit state.
// ============================================================
__device__ void qcnn_producer(const float* __restrict__ sentence, int s0) {
    __shared__ float2 buf[2][NAMP];
    __shared__ float tc[63], ts[63];
    __shared__ float xc[8], xs[8];
    __shared__ float red[8];

    const int tid = threadIdx.x;
    if (tid < 63) { tc[tid] = g_trig[2 * tid]; ts[tid] = g_trig[2 * tid + 1]; }

    const float RT = 0.70710678118654752440f;

    for (int s = s0; s < SEQN; s += NBLK - 1) {
        if (tid < 8) {
            float x = sentence[s * 8 + tid];
            float sn, cs;
            sincosf(2.0f * x, &sn, &cs);
            xc[tid] = cs; xs[tid] = sn;
        }
        __syncthreads();

        float re = (tid == 0) ? 1.0f : 0.0f;
        float im = 0.0f;
        int pb = 0;

        auto H = [&](int q) {
            buf[pb][tid] = make_float2(re, im);
            __syncthreads();
            float2 o = buf[pb][tid ^ (1 << q)];
            pb ^= 1;
            if ((tid >> q) & 1) { re = (o.x - re) * RT; im = (o.y - im) * RT; }
            else                { re = (re + o.x) * RT; im = (im + o.y) * RT; }
        };
        auto PH = [&](int q, float c, float sn) {
            if ((tid >> q) & 1) {
                float nr = re * c - im * sn;
                im = re * sn + im * c;
                re = nr;
            }
        };
        auto RZ = [&](int q, float c, float sn) {
            float ss = ((tid >> q) & 1) ? sn : -sn;
            float nr = re * c - im * ss;
            im = re * ss + im * c;
            re = nr;
        };
        auto RY = [&](int q, float c, float sn) {
            buf[pb][tid] = make_float2(re, im);
            __syncthreads();
            float2 o = buf[pb][tid ^ (1 << q)];
            pb ^= 1;
            float ss = ((tid >> q) & 1) ? sn : -sn;
            re = c * re + ss * o.x;
            im = c * im + ss * o.y;
        };
        auto CNOT = [&](int cq, int tq) {
            buf[pb][tid] = make_float2(re, im);
            __syncthreads();
            int src = ((tid >> cq) & 1) ? (tid ^ (1 << tq)) : tid;
            float2 o = buf[pb][src];
            pb ^= 1;
            re = o.x; im = o.y;
        };
        auto conv = [&](int a, int b, int k) {
            RZ(b, RT, -RT);
            CNOT(b, a);
            RZ(a, tc[k], ts[k]);
            RY(b, tc[k + 1], ts[k + 1]);
            CNOT(a, b);
            RY(b, tc[k + 2], ts[k + 2]);
            CNOT(b, a);
            RZ(a, RT, RT);
        };
        auto pool = [&](int a, int b, int k) {
            RZ(b, RT, -RT);
            CNOT(b, a);
            RZ(a, tc[k], ts[k]);
            RY(b, tc[k + 1], ts[k + 1]);
            CNOT(a, b);
            RY(b, tc[k + 2], ts[k + 2]);
        };

#pragma unroll
        for (int q = 0; q < 8; q++) { H(q); PH(q, xc[q], xs[q]); }

        int k = 0;
        conv(0, 1, k); k += 3;  conv(2, 3, k); k += 3;
        conv(4, 5, k); k += 3;  conv(6, 7, k); k += 3;
        conv(1, 2, k); k += 3;  conv(3, 4, k); k += 3;
        conv(5, 6, k); k += 3;  conv(7, 0, k); k += 3;
        pool(0, 4, k); k += 3;  pool(1, 5, k); k += 3;
        pool(2, 6, k); k += 3;  pool(3, 7, k); k += 3;
        conv(0, 1, k); k += 3;  conv(2, 3, k); k += 3;
        conv(1, 2, k); k += 3;  conv(3, 0, k); k += 3;
        pool(0, 2, k); k += 3;  pool(1, 3, k); k += 3;
        conv(0, 1, k); k += 3;  conv(1, 0, k); k += 3;
        pool(0, 1, k); k += 3;

        float p = re * re + im * im;
        float v = (tid & 128) ? -p : p;
#pragma unroll
        for (int o = 16; o; o >>= 1) v += __shfl_xor_sync(0xFFFFFFFFu, v, o);
        if ((tid & 31) == 0) red[tid >> 5] = v;
        __syncthreads();
        if (tid == 0) {
            float sv = 0.0f;
#pragma unroll
            for (int i = 0; i < 8; i++) sv += red[i];
            g_q[s] = sv + QBIAS;   // single-word data+flag: no fence needed
        }
        __syncthreads();           // protect red[] and xc/xs reuse next sample
    }
}

// ============================================================
// QLSTM sequential scan: 16 lanes of warp 0, block 0 (exclusive SM).
// Quantum layer collapsed analytically to cosine products:
//   z0=c1c2c3, z1=c0c1, z2=c0c1c2, z3=c0c1c2c3
// Activations via exact EX2+RCP:
//   sigmoid: r = 1/(1+2^(-z*log2e)),            act = r
//   tanh(u): r = 1/(1+2^(-2z*log2e)),           act = 2r-1
//   h = ao*tanh(c) = ao - 2*ao/(1+2^(2c*log2e))
// ============================================================
__device__ void qlstm_scan(const float* __restrict__ Wf, const float* __restrict__ bf,
                           const float* __restrict__ Wi, const float* __restrict__ bi,
                           const float* __restrict__ Wu, const float* __restrict__ bu,
                           const float* __restrict__ Wo, const float* __restrict__ bo,
                           const float* __restrict__ thf, const float* __restrict__ thi,
                           const float* __restrict__ thu, const float* __restrict__ tho) {
    const int l = threadIdx.x;
    if (l >= 16) return;

    const int g = l >> 2;
    const int q = l & 3;
    const int base = l & ~3;
    const unsigned M = 0x0000FFFFu;
    const float LOG2E = 1.44269504088896340736f;

    const float* W  = (g == 0) ? Wf  : (g == 1) ? Wi  : (g == 2) ? Wu  : Wo;
    const float* b  = (g == 0) ? bf  : (g == 1) ? bi  : (g == 2) ? bu  : bo;
    const float* th = (g == 0) ? thf : (g == 1) ? thi : (g == 2) ? thu : tho;

    const float W0 = W[q * 5 + 0];
    const float w1 = W[q * 5 + 1], w2 = W[q * 5 + 2];
    const float w3 = W[q * 5 + 3], w4 = W[q * 5 + 4];
    const float ub = b[q] + th[q];

    const bool use0 = (q != 0);
    const bool use2 = (q != 1);
    const bool use3 = (q == 0) || (q == 3);

    const bool isU = (g == 2);
    const float sE   = isU ? (-2.0f * LOG2E) : (-LOG2E);  // exponent scale
    const float Aact = isU ?  2.0f : 1.0f;
    const float Bact = isU ? -1.0f : 0.0f;
    const float C2   = 2.0f * LOG2E;                      // for tanh(c)

    // register prefetch ring (raw channel words; ready iff > 5)
    float qq[PF];
#pragma unroll
    for (int j = 0; j < PF; j++) {
        float v;
        do { v = g_q[j]; } while (v < 5.0f);
        qq[j] = v;
    }

    float c = 0.0f, h0 = 0.0f, h1 = 0.0f, h2 = 0.0f, h3 = 0.0f;

    for (int t0 = 0; t0 < SEQN; t0 += PF) {
#pragma unroll
        for (int j = 0; j < PF; j++) {
            const int t = t0 + j;
            float raw = qq[j];
            if (raw < 5.0f) {                  // producer behind (rare)
                do { raw = g_q[t]; } while (raw < 5.0f);
            }
            const float qv = raw - QBIAS;
            const int tn = t + PF;
            qq[j] = (tn < SEQN) ? g_q[tn] : QBIAS;  // prefetch (checked at use)

            // y = W·[q; h] + b + th   (tree form)
            const float bse = fmaf(W0, qv, ub);
            float A = fmaf(w2, h1, fmaf(w1, h0, bse));
            float B = fmaf(w4, h3, w3 * h2);
            const float y = A + B;

            const float cz = __cosf(y);

            const float c0 = __shfl_sync(M, cz, base + 0);
            const float c1 = __shfl_sync(M, cz, base + 1);
            const float c2 = __shfl_sync(M, cz, base + 2);
            const float c3 = __shfl_sync(M, cz, base + 3);

            const float m0 = use0 ? c0 : 1.0f;
            const float m2 = use2 ? c2 : 1.0f;
            const float m3 = use3 ? c3 : 1.0f;
            const float z  = (c1 * m0) * (m2 * m3);

            const float e   = ex2f(z * sE);
            const float r   = rcpf(1.0f + e);
            const float act = fmaf(Aact, r, Bact);

            const float af = __shfl_sync(M, act, q);
            const float ai = __shfl_sync(M, act, 4 + q);
            const float au = __shfl_sync(M, act, 8 + q);
            const float ao = __shfl_sync(M, act, 12 + q);

            const float iu   = ai * au;
            const float nao2 = -2.0f * ao;      // off critical chain
            c = fmaf(af, c, iu);

            const float E2 = ex2f(c * C2);
            const float rr = rcpf(1.0f + E2);
            const float hq = fmaf(nao2, rr, ao);

            if (g == 0) g_hs[t * 4 + q] = hq;

            h0 = __shfl_sync(M, hq, base + 0);
            h1 = __shfl_sync(M, hq, base + 1);
            h2 = __shfl_sync(M, hq, base + 2);
            h3 = __shfl_sync(M, hq, base + 3);
        }
    }
}

// ============================================================
// Kernel 2 (fused, 148 blocks = 1/SM): block 0 = scan alone on
// its SM; blocks 1..147 = persistent QCNN producers.
// ============================================================
__global__ void __launch_bounds__(NAMP, 1)
fused_kernel(const float* __restrict__ sentence,
             const float* __restrict__ Wf, const float* __restrict__ bf,
             const float* __restrict__ Wi, const float* __restrict__ bi,
             const float* __restrict__ Wu, const float* __restrict__ bu,
             const float* __restrict__ Wo, const float* __restrict__ bo,
             const float* __restrict__ thf, const float* __restrict__ thi,
             const float* __restrict__ thu, const float* __restrict__ tho) {
    if (blockIdx.x == 0) {
        if (threadIdx.x < 32)
            qlstm_scan(Wf, bf, Wi, bi, Wu, bu, Wo, bo, thf, thi, thu, tho);
    } else {
        qcnn_producer(sentence, blockIdx.x - 1);
    }
}

// ============================================================
// Kernel 3: logits + log_softmax. One warp per timestep row.
// ============================================================
__global__ void head_kernel(const float* __restrict__ Wt, const float* __restrict__ bt,
                            float* __restrict__ out) {
    const int warp = (blockIdx.x * blockDim.x + threadIdx.x) >> 5;
    const int lane = threadIdx.x & 31;
    if (warp >= SEQN) return;

    float h0 = g_hs[warp * 4 + 0];
    float h1 = g_hs[warp * 4 + 1];
    float h2 = g_hs[warp * 4 + 2];
    float h3 = g_hs[warp * 4 + 3];

    float l = bt[lane];
    l = fmaf(h0, Wt[lane * 4 + 0], l);
    l = fmaf(h1, Wt[lane * 4 + 1], l);
    l = fmaf(h2, Wt[lane * 4 + 2], l);
    l = fmaf(h3, Wt[lane * 4 + 3], l);

    float m = l;
#pragma unroll
    for (int o = 16; o; o >>= 1) m = fmaxf(m, __shfl_xor_sync(0xFFFFFFFFu, m, o));
    float e = __expf(l - m);
    float sum = e;
#pragma unroll
    for (int o = 16; o; o >>= 1) sum += __shfl_xor_sync(0xFFFFFFFFu, sum, o);

    out[warp * 32 + lane] = (l - m) - __logf(sum);
}

// ============================================================
extern "C" void kernel_launch(void* const* d_in, const int* in_sizes, int n_in,
                              void* d_out, int out_size) {
    const float* sentence = (const float*)d_in[0];
    const float* qcnn_w   = (const float*)d_in[1];
    const float* Wf  = (const float*)d_in[2];
    const float* bf  = (const float*)d_in[3];
    const float* Wi  = (const float*)d_in[4];
    const float* bi  = (const float*)d_in[5];
    const float* Wu  = (const float*)d_in[6];
    const float* bu  = (const float*)d_in[7];
    const float* Wo  = (const float*)d_in[8];
    const float* bo  = (const float*)d_in[9];
    const float* thf = (const float*)d_in[10];
    const float* thi = (const float*)d_in[11];
    const float* thu = (const float*)d_in[12];
    const float* tho = (const float*)d_in[13];
    const float* Wt  = (const float*)d_in[14];
    const float* bt  = (const float*)d_in[15];
    float* out = (float*)d_out;

    prep_kernel<<<1, 256>>>(qcnn_w);
    fused_kernel<<<NBLK, NAMP>>>(sentence,
                                 Wf, bf, Wi, bi, Wu, bu, Wo, bo,
                                 thf, thi, thu, tho);
    head_kernel<<<(SEQN * 32) / 256, 256>>>(Wt, bt, out);
}

// round 4
// speedup vs baseline: 3.2660x; 1.4234x over previous
#include <cuda_runtime.h>
#include <math.h>

#define SEQN 2048
#define NAMP 256
#define PF 16
#define NBLK 148          // #SMs: block 0 = scan (own SM), 1..147 = producers

#define NOT_READY -1.0e30f
#define QBIAS 10.0f

// ---- device scratch (no allocations allowed) ----
__device__ float g_trig[2 * 63];            // cos,sin of w[j]/2
__device__ volatile float g_q[SEQN + PF];   // data+flag channel: ready iff > 5
__device__ float g_hs[SEQN * 4];            // LSTM hidden states

// ============================================================
// Kernel 1: trig precompute + q-channel sentinel init (+padding)
// ============================================================
__global__ void prep_kernel(const float* __restrict__ w) {
    int j = threadIdx.x;
    if (j < 63) {
        float s, c;
        sincosf(0.5f * w[j], &s, &c);
        g_trig[2 * j]     = c;
        g_trig[2 * j + 1] = s;
    }
    for (int i = j; i < SEQN + PF; i += blockDim.x)
        g_q[i] = (i < SEQN) ? NOT_READY : QBIAS;   // padding pre-ready
}

// ============================================================
// QCNN producer: persistent block handles samples s0, s0+147, ...
// ============================================================
__device__ void qcnn_producer(const float* __restrict__ sentence, int s0) {
    __shared__ float2 buf[2][NAMP];
    __shared__ float tc[63], ts[63];
    __shared__ float xc[8], xs[8];
    __shared__ float red[8];

    const int tid = threadIdx.x;
    if (tid < 63) { tc[tid] = g_trig[2 * tid]; ts[tid] = g_trig[2 * tid + 1]; }

    const float RT = 0.70710678118654752440f;

    for (int s = s0; s < SEQN; s += NBLK - 1) {
        if (tid < 8) {
            float x = sentence[s * 8 + tid];
            float sn, cs;
            sincosf(2.0f * x, &sn, &cs);
            xc[tid] = cs; xs[tid] = sn;
        }
        __syncthreads();

        float re = (tid == 0) ? 1.0f : 0.0f;
        float im = 0.0f;
        int pb = 0;

        auto H = [&](int q) {
            buf[pb][tid] = make_float2(re, im);
            __syncthreads();
            float2 o = buf[pb][tid ^ (1 << q)];
            pb ^= 1;
            if ((tid >> q) & 1) { re = (o.x - re) * RT; im = (o.y - im) * RT; }
            else                { re = (re + o.x) * RT; im = (im + o.y) * RT; }
        };
        auto PH = [&](int q, float c, float sn) {
            if ((tid >> q) & 1) {
                float nr = re * c - im * sn;
                im = re * sn + im * c;
                re = nr;
            }
        };
        auto RZ = [&](int q, float c, float sn) {
            float ss = ((tid >> q) & 1) ? sn : -sn;
            float nr = re * c - im * ss;
            im = re * ss + im * c;
            re = nr;
        };
        auto RY = [&](int q, float c, float sn) {
            buf[pb][tid] = make_float2(re, im);
            __syncthreads();
            float2 o = buf[pb][tid ^ (1 << q)];
            pb ^= 1;
            float ss = ((tid >> q) & 1) ? sn : -sn;
            re = c * re + ss * o.x;
            im = c * im + ss * o.y;
        };
        auto CNOT = [&](int cq, int tq) {
            buf[pb][tid] = make_float2(re, im);
            __syncthreads();
            int src = ((tid >> cq) & 1) ? (tid ^ (1 << tq)) : tid;
            float2 o = buf[pb][src];
            pb ^= 1;
            re = o.x; im = o.y;
        };
        auto conv = [&](int a, int b, int k) {
            RZ(b, RT, -RT);
            CNOT(b, a);
            RZ(a, tc[k], ts[k]);
            RY(b, tc[k + 1], ts[k + 1]);
            CNOT(a, b);
            RY(b, tc[k + 2], ts[k + 2]);
            CNOT(b, a);
            RZ(a, RT, RT);
        };
        auto pool = [&](int a, int b, int k) {
            RZ(b, RT, -RT);
            CNOT(b, a);
            RZ(a, tc[k], ts[k]);
            RY(b, tc[k + 1], ts[k + 1]);
            CNOT(a, b);
            RY(b, tc[k + 2], ts[k + 2]);
        };

#pragma unroll
        for (int q = 0; q < 8; q++) { H(q); PH(q, xc[q], xs[q]); }

        int k = 0;
        conv(0, 1, k); k += 3;  conv(2, 3, k); k += 3;
        conv(4, 5, k); k += 3;  conv(6, 7, k); k += 3;
        conv(1, 2, k); k += 3;  conv(3, 4, k); k += 3;
        conv(5, 6, k); k += 3;  conv(7, 0, k); k += 3;
        pool(0, 4, k); k += 3;  pool(1, 5, k); k += 3;
        pool(2, 6, k); k += 3;  pool(3, 7, k); k += 3;
        conv(0, 1, k); k += 3;  conv(2, 3, k); k += 3;
        conv(1, 2, k); k += 3;  conv(3, 0, k); k += 3;
        pool(0, 2, k); k += 3;  pool(1, 3, k); k += 3;
        conv(0, 1, k); k += 3;  conv(1, 0, k); k += 3;
        pool(0, 1, k); k += 3;

        float p = re * re + im * im;
        float v = (tid & 128) ? -p : p;
#pragma unroll
        for (int o = 16; o; o >>= 1) v += __shfl_xor_sync(0xFFFFFFFFu, v, o);
        if ((tid & 31) == 0) red[tid >> 5] = v;
        __syncthreads();
        if (tid == 0) {
            float sv = 0.0f;
#pragma unroll
            for (int i = 0; i < 8; i++) sv += red[i];
            g_q[s] = sv + QBIAS;   // single-word data+flag
        }
        __syncthreads();
    }
}

// ============================================================
// Runtime poly fit: deg-7 (in v) interpolation of g(v)=tanh(sqrt v)/sqrt v
// at 8 Chebyshev nodes on [0,vmax], via Newton divided differences,
// converted to monomial coefficients. tanh(x) ~= x * P(x^2).
// Executed redundantly by all scan lanes (uniform, register-only).
// ============================================================
__device__ __forceinline__ void fit_g(float vmax, float* C) {
    const float cs0 = 0.98078528f, cs1 = 0.83146961f,
                cs2 = 0.55557023f, cs3 = 0.19509032f;
    float v[8], d[8];
    v[0] = 0.5f * vmax * (1.0f + cs0);
    v[1] = 0.5f * vmax * (1.0f + cs1);
    v[2] = 0.5f * vmax * (1.0f + cs2);
    v[3] = 0.5f * vmax * (1.0f + cs3);
    v[4] = 0.5f * vmax * (1.0f - cs3);
    v[5] = 0.5f * vmax * (1.0f - cs2);
    v[6] = 0.5f * vmax * (1.0f - cs1);
    v[7] = 0.5f * vmax * (1.0f - cs0);
#pragma unroll
    for (int k = 0; k < 8; k++) {
        float x = sqrtf(v[k]);
        d[k] = tanhf(x) / x;
    }
#pragma unroll
    for (int j = 1; j < 8; j++)
#pragma unroll
        for (int k = 7; k >= 1; k--)
            if (k >= j) d[k] = (d[k] - d[k - 1]) / (v[k] - v[k - j]);
#pragma unroll
    for (int i = 0; i < 8; i++) C[i] = 0.0f;
    C[0] = d[7];
#pragma unroll
    for (int k = 6; k >= 0; k--) {
#pragma unroll
        for (int i = 7; i >= 1; i--) C[i] = C[i - 1] - v[k] * C[i];
        C[0] = d[k] - v[k] * C[0];
    }
}

// deg-7 Estrin in u: returns P(u)
__device__ __forceinline__ float estrin8(const float* K, float u) {
    float u2 = u * u;
    float u4 = u2 * u2;
    float a = fmaf(K[1], u, K[0]);
    float b = fmaf(K[3], u, K[2]);
    float c = fmaf(K[5], u, K[4]);
    float d = fmaf(K[7], u, K[6]);
    float ab = fmaf(b, u2, a);
    float cd = fmaf(d, u2, c);
    return fmaf(cd, u4, ab);
}

// ============================================================
// QLSTM sequential scan: warp 0 of block 0 (exclusive SM), 32 lanes
// (upper 16 mirror lower 16). Quantum layer collapsed to cosine
// products; all activations pure-FMA polynomials:
//   sigma(z) = 0.5 + z*0.25*gA(z^2/4)   (z in [-1,1])
//   tanh(z)  = z*gA(z^2)
//   tanh(c)  = c*gB(c^2)                (|c| <= 2.071 provably)
// ============================================================
__device__ void qlstm_scan(const float* __restrict__ Wf, const float* __restrict__ bf,
                           const float* __restrict__ Wi, const float* __restrict__ bi,
                           const float* __restrict__ Wu, const float* __restrict__ bu,
                           const float* __restrict__ Wo, const float* __restrict__ bo,
                           const float* __restrict__ thf, const float* __restrict__ thi,
                           const float* __restrict__ thu, const float* __restrict__ tho) {
    const int l = threadIdx.x;          // 0..31, all active
    const int g = (l >> 2) & 3;
    const int q = l & 3;
    const int base = l & ~3;
    const unsigned M = 0xFFFFFFFFu;

    const float* W  = (g == 0) ? Wf  : (g == 1) ? Wi  : (g == 2) ? Wu  : Wo;
    const float* b  = (g == 0) ? bf  : (g == 1) ? bi  : (g == 2) ? bu  : bo;
    const float* th = (g == 0) ? thf : (g == 1) ? thi : (g == 2) ? thu : tho;

    const float W0 = W[q * 5 + 0];
    const float w1 = W[q * 5 + 1], w2 = W[q * 5 + 2];
    const float w3 = W[q * 5 + 3], w4 = W[q * 5 + 4];
    const float ub = b[q] + th[q];

    const bool use0 = (q != 0);
    const bool use2 = (q != 1);
    const bool use3 = (q == 0) || (q == 3);
    const bool isU  = (g == 2);

    // fit activation polynomials (runs during producer warm-up)
    float gA[8], gB[8];
    fit_g(1.0f, gA);      // tanh on [-1,1]
    fit_g(4.35f, gB);     // tanh on [-2.085, 2.085] (covers |c|<=2.071)

    // per-lane act coeffs: u-lane tanh(z)=z*gA(z^2);
    // sigma lanes: 0.5 + z*0.25*gA(z^2/4) -> fold 4^-j into coeffs
    float aK[8];
    {
        float s = 0.25f;
#pragma unroll
        for (int j = 0; j < 8; j++) {
            aK[j] = isU ? gA[j] : gA[j] * s;
            s *= 0.25f;
        }
    }
    const float Kc = isU ? 0.0f : 0.5f;

    // prologue: wait for first block, precompute biased bases
    float nq[PF], bq[PF];
    {
        float mn;
        do {
            mn = 1e30f;
#pragma unroll
            for (int j = 0; j < PF; j++) {
                float x = g_q[j];
                nq[j] = x;
                mn = fminf(mn, x);
            }
        } while (mn < 5.0f);
#pragma unroll
        for (int j = 0; j < PF; j++) bq[j] = fmaf(W0, nq[j] - QBIAS, ub);
    }

    float c = 0.0f, h0 = 0.0f, h1 = 0.0f, h2 = 0.0f, h3 = 0.0f;

    for (int t0 = 0; t0 < SEQN; t0 += PF) {
        // prefetch next block (off critical path; padding pre-ready)
#pragma unroll
        for (int j = 0; j < PF; j++) nq[j] = g_q[t0 + PF + j];

        // 16 pure-math steps
#pragma unroll
        for (int j = 0; j < PF; j++) {
            const int t = t0 + j;

            // y = bse + w.h  (tree)
            float A = fmaf(w2, h1, fmaf(w1, h0, bq[j]));
            float B = fmaf(w4, h3, w3 * h2);
            const float y = A + B;

            const float cz = __cosf(y);

            const float c0 = __shfl_sync(M, cz, base + 0);
            const float c1 = __shfl_sync(M, cz, base + 1);
            const float c2 = __shfl_sync(M, cz, base + 2);
            const float c3 = __shfl_sync(M, cz, base + 3);

            const float m0 = use0 ? c0 : 1.0f;
            const float m2 = use2 ? c2 : 1.0f;
            const float m3 = use3 ? c3 : 1.0f;
            const float z  = (c1 * m0) * (m2 * m3);

            const float act = fmaf(z, estrin8(aK, z * z), Kc);

            const float af = __shfl_sync(M, act, q);
            const float ai = __shfl_sync(M, act, 4 + q);
            const float au = __shfl_sync(M, act, 8 + q);
            const float ao = __shfl_sync(M, act, 12 + q);

            c = fmaf(af, c, ai * au);

            // h = ao * tanh(c) = (ao*c) * gB(c^2)
            const float hq = (ao * c) * estrin8(gB, c * c);

            if (l < 4) g_hs[t * 4 + q] = hq;

            h0 = __shfl_sync(M, hq, base + 0);
            h1 = __shfl_sync(M, hq, base + 1);
            h2 = __shfl_sync(M, hq, base + 2);
            h3 = __shfl_sync(M, hq, base + 3);
        }

        // verify prefetched block; spin-reload only if producer behind (rare)
        float mn = nq[0];
#pragma unroll
        for (int j = 1; j < PF; j++) mn = fminf(mn, nq[j]);
        while (mn < 5.0f) {
            mn = 1e30f;
#pragma unroll
            for (int j = 0; j < PF; j++) {
                float x = g_q[t0 + PF + j];
                nq[j] = x;
                mn = fminf(mn, x);
            }
        }
#pragma unroll
        for (int j = 0; j < PF; j++) bq[j] = fmaf(W0, nq[j] - QBIAS, ub);
    }
}

// ============================================================
// Fused kernel: 148 blocks (1/SM). Block 0 warp 0 = scan;
// blocks 1..147 = persistent QCNN producers.
// ============================================================
__global__ void __launch_bounds__(NAMP, 1)
fused_kernel(const float* __restrict__ sentence,
             const float* __restrict__ Wf, const float* __restrict__ bf,
             const float* __restrict__ Wi, const float* __restrict__ bi,
             const float* __restrict__ Wu, const float* __restrict__ bu,
             const float* __restrict__ Wo, const float* __restrict__ bo,
             const float* __restrict__ thf, const float* __restrict__ thi,
             const float* __restrict__ thu, const float* __restrict__ tho) {
    if (blockIdx.x == 0) {
        if (threadIdx.x < 32)
            qlstm_scan(Wf, bf, Wi, bi, Wu, bu, Wo, bo, thf, thi, thu, tho);
    } else {
        qcnn_producer(sentence, blockIdx.x - 1);
    }
}

// ============================================================
// Kernel 3: logits + log_softmax. One warp per timestep row.
// ============================================================
__global__ void head_kernel(const float* __restrict__ Wt, const float* __restrict__ bt,
                            float* __restrict__ out) {
    const int warp = (blockIdx.x * blockDim.x + threadIdx.x) >> 5;
    const int lane = threadIdx.x & 31;
    if (warp >= SEQN) return;

    float h0 = g_hs[warp * 4 + 0];
    float h1 = g_hs[warp * 4 + 1];
    float h2 = g_hs[warp * 4 + 2];
    float h3 = g_hs[warp * 4 + 3];

    float l = bt[lane];
    l = fmaf(h0, Wt[lane * 4 + 0], l);
    l = fmaf(h1, Wt[lane * 4 + 1], l);
    l = fmaf(h2, Wt[lane * 4 + 2], l);
    l = fmaf(h3, Wt[lane * 4 + 3], l);

    float m = l;
#pragma unroll
    for (int o = 16; o; o >>= 1) m = fmaxf(m, __shfl_xor_sync(0xFFFFFFFFu, m, o));
    float e = __expf(l - m);
    float sum = e;
#pragma unroll
    for (int o = 16; o; o >>= 1) sum += __shfl_xor_sync(0xFFFFFFFFu, sum, o);

    out[warp * 32 + lane] = (l - m) - __logf(sum);
}

// ============================================================
extern "C" void kernel_launch(void* const* d_in, const int* in_sizes, int n_in,
                              void* d_out, int out_size) {
    const float* sentence = (const float*)d_in[0];
    const float* qcnn_w   = (const float*)d_in[1];
    const float* Wf  = (const float*)d_in[2];
    const float* bf  = (const float*)d_in[3];
    const float* Wi  = (const float*)d_in[4];
    const float* bi  = (const float*)d_in[5];
    const float* Wu  = (const float*)d_in[6];
    const float* bu  = (const float*)d_in[7];
    const float* Wo  = (const float*)d_in[8];
    const float* bo  = (const float*)d_in[9];
    const float* thf = (const float*)d_in[10];
    const float* thi = (const float*)d_in[11];
    const float* thu = (const float*)d_in[12];
    const float* tho = (const float*)d_in[13];
    const float* Wt  = (const float*)d_in[14];
    const float* bt  = (const float*)d_in[15];
    float* out = (float*)d_out;

    prep_kernel<<<1, 256>>>(qcnn_w);
    fused_kernel<<<NBLK, NAMP>>>(sentence,
                                 Wf, bf, Wi, bi, Wu, bu, Wo, bo,
                                 thf, thi, thu, tho);
    head_kernel<<<(SEQN * 32) / 256, 256>>>(Wt, bt, out);
}

// round 5
// speedup vs baseline: 18.3493x; 5.6182x over previous
#include <cuda_runtime.h>
#include <math.h>

#define SEQN 2048
#define PF 16
#define NBLK 148            // #SMs; blocks 0..15 = scan chunks, 16..147 = producers
#define NCHUNK 16
#define CH_LEN 128          // SEQN / NCHUNK
#define WARM 64             // warm-up steps (0.731^64 ~ 2e-9)
#define NPB (NBLK - NCHUNK) // 132 producer blocks
#define PSTRIDE (NPB * 8)   // samples per sweep (8 warps/block)

#define NOT_READY -1.0e30f
#define QBIAS 10.0f

// ---- device scratch (no allocations allowed) ----
__device__ float g_trig[2 * 63];            // cos,sin of w[j]/2
__device__ volatile float g_q[SEQN + PF];   // data+flag channel: ready iff > 5
__device__ float g_hs[SEQN * 4];            // LSTM hidden states

// ============================================================
// Kernel 1: trig precompute + q-channel sentinel init (+padding)
// ============================================================
__global__ void prep_kernel(const float* __restrict__ w) {
    int j = threadIdx.x;
    if (j < 63) {
        float s, c;
        sincosf(0.5f * w[j], &s, &c);
        g_trig[2 * j]     = c;
        g_trig[2 * j + 1] = s;
    }
    for (int i = j; i < SEQN + PF; i += blockDim.x)
        g_q[i] = (i < SEQN) ? NOT_READY : QBIAS;   // padding pre-ready
}

// ============================================================
// Warp-per-sample QCNN: 256 amplitudes, 8 per lane in registers.
// amp index = (lane << 3) | j : qubits 0-2 = j bits (in-register),
// qubits 3-7 = lane bits (shfl.xor). No __syncthreads anywhere.
// ============================================================
#define FULLM 0xFFFFFFFFu
#define RTC 0.70710678118654752440f

template<int Q>
__device__ __forceinline__ void RZg(float (&ar)[8], float (&ai)[8],
                                    float c, float s, int lane) {
#pragma unroll
    for (int j = 0; j < 8; j++) {
        int b = (Q < 3) ? ((j >> Q) & 1) : ((lane >> (Q - 3)) & 1);
        float ss = b ? s : -s;
        float nr = ar[j] * c - ai[j] * ss;
        ai[j] = fmaf(ar[j], ss, ai[j] * c);
        ar[j] = nr;
    }
}

template<int Q>
__device__ __forceinline__ void PHg(float (&ar)[8], float (&ai)[8],
                                    float c, float s, int lane) {
#pragma unroll
    for (int j = 0; j < 8; j++) {
        int b = (Q < 3) ? ((j >> Q) & 1) : ((lane >> (Q - 3)) & 1);
        float cc = b ? c : 1.0f;
        float ss = b ? s : 0.0f;
        float nr = ar[j] * cc - ai[j] * ss;
        ai[j] = fmaf(ar[j], ss, ai[j] * cc);
        ar[j] = nr;
    }
}

template<int Q>
__device__ __forceinline__ void Hg(float (&ar)[8], float (&ai)[8], int lane) {
    if (Q < 3) {
#pragma unroll
        for (int j = 0; j < 8; j++)
            if (((j >> Q) & 1) == 0) {
                int j1 = j | (1 << Q);
                float r0 = ar[j], r1 = ar[j1], i0 = ai[j], i1 = ai[j1];
                ar[j]  = (r0 + r1) * RTC;  ar[j1] = (r0 - r1) * RTC;
                ai[j]  = (i0 + i1) * RTC;  ai[j1] = (i0 - i1) * RTC;
            }
    } else {
        const int m = 1 << (Q - 3);
        float sgn = ((lane >> (Q - 3)) & 1) ? -1.0f : 1.0f;
#pragma unroll
        for (int j = 0; j < 8; j++) {
            float orr = __shfl_xor_sync(FULLM, ar[j], m);
            float oii = __shfl_xor_sync(FULLM, ai[j], m);
            ar[j] = fmaf(sgn, ar[j], orr) * RTC;
            ai[j] = fmaf(sgn, ai[j], oii) * RTC;
        }
    }
}

template<int Q>
__device__ __forceinline__ void RYg(float (&ar)[8], float (&ai)[8],
                                    float c, float s, int lane) {
    if (Q < 3) {
#pragma unroll
        for (int j = 0; j < 8; j++)
            if (((j >> Q) & 1) == 0) {
                int j1 = j | (1 << Q);
                float r0 = ar[j], r1 = ar[j1], i0 = ai[j], i1 = ai[j1];
                ar[j]  = fmaf(c, r0, -s * r1);  ar[j1] = fmaf(s, r0, c * r1);
                ai[j]  = fmaf(c, i0, -s * i1);  ai[j1] = fmaf(s, i0, c * i1);
            }
    } else {
        const int m = 1 << (Q - 3);
        float ss = ((lane >> (Q - 3)) & 1) ? s : -s;
#pragma unroll
        for (int j = 0; j < 8; j++) {
            float orr = __shfl_xor_sync(FULLM, ar[j], m);
            float oii = __shfl_xor_sync(FULLM, ai[j], m);
            ar[j] = fmaf(c, ar[j], ss * orr);
            ai[j] = fmaf(c, ai[j], ss * oii);
        }
    }
}

template<int CQ, int TQ>
__device__ __forceinline__ void CXg(float (&ar)[8], float (&ai)[8], int lane) {
    if (CQ < 3 && TQ < 3) {
#pragma unroll
        for (int j = 0; j < 8; j++)
            if ((((j >> CQ) & 1) == 1) && (((j >> TQ) & 1) == 0)) {
                int j1 = j | (1 << TQ);
                float tr = ar[j]; ar[j] = ar[j1]; ar[j1] = tr;
                float ti = ai[j]; ai[j] = ai[j1]; ai[j1] = ti;
            }
    } else if (CQ < 3) {              // target cross-lane
        const int m = 1 << (TQ - 3);
#pragma unroll
        for (int j = 0; j < 8; j++)
            if (((j >> CQ) & 1) == 1) {
                ar[j] = __shfl_xor_sync(FULLM, ar[j], m);
                ai[j] = __shfl_xor_sync(FULLM, ai[j], m);
            }
    } else if (TQ < 3) {              // control in lane, target local
        int b = (lane >> (CQ - 3)) & 1;
#pragma unroll
        for (int j = 0; j < 8; j++)
            if (((j >> TQ) & 1) == 0) {
                int j1 = j | (1 << TQ);
                float r0 = ar[j], r1 = ar[j1];
                ar[j] = b ? r1 : r0;  ar[j1] = b ? r0 : r1;
                float i0 = ai[j], i1 = ai[j1];
                ai[j] = b ? i1 : i0;  ai[j1] = b ? i0 : i1;
            }
    } else {                          // both cross-lane
        const int m = 1 << (TQ - 3);
        int b = (lane >> (CQ - 3)) & 1;
#pragma unroll
        for (int j = 0; j < 8; j++) {
            float orr = __shfl_xor_sync(FULLM, ar[j], m);
            float oii = __shfl_xor_sync(FULLM, ai[j], m);
            ar[j] = b ? orr : ar[j];
            ai[j] = b ? oii : ai[j];
        }
    }
}

template<int A, int B>
__device__ __forceinline__ void conv_t(float (&ar)[8], float (&ai)[8],
                                       const float* tc, const float* ts,
                                       int k, int lane) {
    RZg<B>(ar, ai, RTC, -RTC, lane);
    CXg<B, A>(ar, ai, lane);
    RZg<A>(ar, ai, tc[k], ts[k], lane);
    RYg<B>(ar, ai, tc[k + 1], ts[k + 1], lane);
    CXg<A, B>(ar, ai, lane);
    RYg<B>(ar, ai, tc[k + 2], ts[k + 2], lane);
    CXg<B, A>(ar, ai, lane);
    RZg<A>(ar, ai, RTC, RTC, lane);
}

template<int A, int B>
__device__ __forceinline__ void pool_t(float (&ar)[8], float (&ai)[8],
                                       const float* tc, const float* ts,
                                       int k, int lane) {
    RZg<B>(ar, ai, RTC, -RTC, lane);
    CXg<B, A>(ar, ai, lane);
    RZg<A>(ar, ai, tc[k], ts[k], lane);
    RYg<B>(ar, ai, tc[k + 1], ts[k + 1], lane);
    CXg<A, B>(ar, ai, lane);
    RYg<B>(ar, ai, tc[k + 2], ts[k + 2], lane);
}

__device__ void qcnn_warp(const float* __restrict__ sentence, int s,
                          const float* tc, const float* ts, int lane) {
    float ar[8], ai[8];
#pragma unroll
    for (int j = 0; j < 8; j++) { ar[j] = 0.0f; ai[j] = 0.0f; }
    if (lane == 0) ar[0] = 1.0f;

    float myC = 1.0f, myS = 0.0f;
    if (lane < 8) {
        float x = sentence[s * 8 + lane];
        sincosf(2.0f * x, &myS, &myC);
    }

#define FM(Q) { Hg<Q>(ar, ai, lane); \
                float pc = __shfl_sync(FULLM, myC, Q); \
                float ps = __shfl_sync(FULLM, myS, Q); \
                PHg<Q>(ar, ai, pc, ps, lane); }
    FM(0) FM(1) FM(2) FM(3) FM(4) FM(5) FM(6) FM(7)
#undef FM

    conv_t<0, 1>(ar, ai, tc, ts, 0, lane);
    conv_t<2, 3>(ar, ai, tc, ts, 3, lane);
    conv_t<4, 5>(ar, ai, tc, ts, 6, lane);
    conv_t<6, 7>(ar, ai, tc, ts, 9, lane);
    conv_t<1, 2>(ar, ai, tc, ts, 12, lane);
    conv_t<3, 4>(ar, ai, tc, ts, 15, lane);
    conv_t<5, 6>(ar, ai, tc, ts, 18, lane);
    conv_t<7, 0>(ar, ai, tc, ts, 21, lane);
    pool_t<0, 4>(ar, ai, tc, ts, 24, lane);
    pool_t<1, 5>(ar, ai, tc, ts, 27, lane);
    pool_t<2, 6>(ar, ai, tc, ts, 30, lane);
    pool_t<3, 7>(ar, ai, tc, ts, 33, lane);
    conv_t<0, 1>(ar, ai, tc, ts, 36, lane);
    conv_t<2, 3>(ar, ai, tc, ts, 39, lane);
    conv_t<1, 2>(ar, ai, tc, ts, 42, lane);
    conv_t<3, 0>(ar, ai, tc, ts, 45, lane);
    pool_t<0, 2>(ar, ai, tc, ts, 48, lane);
    pool_t<1, 3>(ar, ai, tc, ts, 51, lane);
    conv_t<0, 1>(ar, ai, tc, ts, 54, lane);
    conv_t<1, 0>(ar, ai, tc, ts, 57, lane);
    pool_t<0, 1>(ar, ai, tc, ts, 60, lane);

    float v = 0.0f;
#pragma unroll
    for (int j = 0; j < 8; j++) v += ar[j] * ar[j] + ai[j] * ai[j];
    if ((lane >> 4) & 1) v = -v;               // Z on qubit 7 = lane bit 4
#pragma unroll
    for (int o = 16; o; o >>= 1) v += __shfl_xor_sync(FULLM, v, o);
    if (lane == 0) g_q[s] = v + QBIAS;         // single-word data+flag
}

// ============================================================
// Runtime poly fit (8 Chebyshev nodes): tanh(x) ~= x * P(x^2)
// ============================================================
__device__ __forceinline__ void fit_g(float vmax, float* C) {
    const float cs0 = 0.98078528f, cs1 = 0.83146961f,
                cs2 = 0.55557023f, cs3 = 0.19509032f;
    float v[8], d[8];
    v[0] = 0.5f * vmax * (1.0f + cs0);
    v[1] = 0.5f * vmax * (1.0f + cs1);
    v[2] = 0.5f * vmax * (1.0f + cs2);
    v[3] = 0.5f * vmax * (1.0f + cs3);
    v[4] = 0.5f * vmax * (1.0f - cs3);
    v[5] = 0.5f * vmax * (1.0f - cs2);
    v[6] = 0.5f * vmax * (1.0f - cs1);
    v[7] = 0.5f * vmax * (1.0f - cs0);
#pragma unroll
    for (int k = 0; k < 8; k++) {
        float x = sqrtf(v[k]);
        d[k] = tanhf(x) / x;
    }
#pragma unroll
    for (int j = 1; j < 8; j++)
#pragma unroll
        for (int k = 7; k >= 1; k--)
            if (k >= j) d[k] = (d[k] - d[k - 1]) / (v[k] - v[k - j]);
#pragma unroll
    for (int i = 0; i < 8; i++) C[i] = 0.0f;
    C[0] = d[7];
#pragma unroll
    for (int k = 6; k >= 0; k--) {
#pragma unroll
        for (int i = 7; i >= 1; i--) C[i] = C[i - 1] - v[k] * C[i];
        C[0] = d[k] - v[k] * C[0];
    }
}

__device__ __forceinline__ float estrin8(const float* K, float u) {
    float u2 = u * u;
    float u4 = u2 * u2;
    float a = fmaf(K[1], u, K[0]);
    float b = fmaf(K[3], u, K[2]);
    float c = fmaf(K[5], u, K[4]);
    float d = fmaf(K[7], u, K[6]);
    float ab = fmaf(b, u2, a);
    float cd = fmaf(d, u2, c);
    return fmaf(cd, u4, ab);
}

// ============================================================
// Chunked QLSTM scan: chunk owns t in [begin, begin+128), warm-up
// from zero state at begin-64 (contraction f <= sigma(1)=0.731
// makes truncation ~2e-9). Warp 0 of blocks 0..15, 32 lanes.
// ============================================================
__device__ void qlstm_scan(int chunk,
                           const float* __restrict__ Wf, const float* __restrict__ bf,
                           const float* __restrict__ Wi, const float* __restrict__ bi,
                           const float* __restrict__ Wu, const float* __restrict__ bu,
                           const float* __restrict__ Wo, const float* __restrict__ bo,
                           const float* __restrict__ thf, const float* __restrict__ thi,
                           const float* __restrict__ thu, const float* __restrict__ tho) {
    const int l = threadIdx.x;          // 0..31
    const int g = (l >> 2) & 3;
    const int q = l & 3;
    const int base = l & ~3;
    const unsigned M = FULLM;

    const int begin = chunk * CH_LEN;
    const int warm0 = (chunk == 0) ? 0 : begin - WARM;
    const int end   = begin + CH_LEN;

    const float* W  = (g == 0) ? Wf  : (g == 1) ? Wi  : (g == 2) ? Wu  : Wo;
    const float* b  = (g == 0) ? bf  : (g == 1) ? bi  : (g == 2) ? bu  : bo;
    const float* th = (g == 0) ? thf : (g == 1) ? thi : (g == 2) ? thu : tho;

    const float W0 = W[q * 5 + 0];
    const float w1 = W[q * 5 + 1], w2 = W[q * 5 + 2];
    const float w3 = W[q * 5 + 3], w4 = W[q * 5 + 4];
    const float ub = b[q] + th[q];

    const bool use0 = (q != 0);
    const bool use2 = (q != 1);
    const bool use3 = (q == 0) || (q == 3);
    const bool isU  = (g == 2);

    float gA[8], gB[8];
    fit_g(1.0f, gA);      // tanh on [-1,1]
    fit_g(4.35f, gB);     // tanh on [-2.085,2.085] (|c| <= 2.071)

    float aK[8];
    {
        float s = 0.25f;
#pragma unroll
        for (int j = 0; j < 8; j++) {
            aK[j] = isU ? gA[j] : gA[j] * s;
            s *= 0.25f;
        }
    }
    const float Kc = isU ? 0.0f : 0.5f;

    // prologue: wait for first block of this chunk's window
    float nq[PF], bq[PF];
    {
        float mn;
        do {
            mn = 1e30f;
#pragma unroll
            for (int j = 0; j < PF; j++) {
                float x = g_q[warm0 + j];
                nq[j] = x;
                mn = fminf(mn, x);
            }
        } while (mn < 5.0f);
#pragma unroll
        for (int j = 0; j < PF; j++) bq[j] = fmaf(W0, nq[j] - QBIAS, ub);
    }

    float c = 0.0f, h0 = 0.0f, h1 = 0.0f, h2 = 0.0f, h3 = 0.0f;

    for (int t0 = warm0; t0 < end; t0 += PF) {
        const bool wr = (l < 4) && (t0 >= begin);   // block-uniform store predicate
        // prefetch next block (off chain; padding pre-ready)
#pragma unroll
        for (int j = 0; j < PF; j++) nq[j] = g_q[t0 + PF + j];

#pragma unroll
        for (int j = 0; j < PF; j++) {
            const int t = t0 + j;

            float A = fmaf(w2, h1, fmaf(w1, h0, bq[j]));
            float B = fmaf(w4, h3, w3 * h2);
            const float y = A + B;

            const float cz = __cosf(y);

            const float c0 = __shfl_sync(M, cz, base + 0);
            const float c1 = __shfl_sync(M, cz, base + 1);
            const float c2 = __shfl_sync(M, cz, base + 2);
            const float c3 = __shfl_sync(M, cz, base + 3);

            const float m0 = use0 ? c0 : 1.0f;
            const float m2 = use2 ? c2 : 1.0f;
            const float m3 = use3 ? c3 : 1.0f;
            const float z  = (c1 * m0) * (m2 * m3);

            const float act = fmaf(z, estrin8(aK, z * z), Kc);

            const float af = __shfl_sync(M, act, q);
            const float ai = __shfl_sync(M, act, 4 + q);
            const float au = __shfl_sync(M, act, 8 + q);
            const float ao = __shfl_sync(M, act, 12 + q);

            c = fmaf(af, c, ai * au);

            const float hq = (ao * c) * estrin8(gB, c * c);

            if (wr) g_hs[t * 4 + q] = hq;

            h0 = __shfl_sync(M, hq, base + 0);
            h1 = __shfl_sync(M, hq, base + 1);
            h2 = __shfl_sync(M, hq, base + 2);
            h3 = __shfl_sync(M, hq, base + 3);
        }

        // verify prefetched block; spin only if producer behind
        float mn = nq[0];
#pragma unroll
        for (int j = 1; j < PF; j++) mn = fminf(mn, nq[j]);
        while (mn < 5.0f) {
            mn = 1e30f;
#pragma unroll
            for (int j = 0; j < PF; j++) {
                float x = g_q[t0 + PF + j];
                nq[j] = x;
                mn = fminf(mn, x);
            }
        }
#pragma unroll
        for (int j = 0; j < PF; j++) bq[j] = fmaf(W0, nq[j] - QBIAS, ub);
    }
}

// ============================================================
// Fused kernel: 148 blocks (1/SM). Blocks 0..15 = scan chunks
// (warp 0 only); blocks 16..147 = producers (8 warps x samples).
// ============================================================
__global__ void __launch_bounds__(256, 1)
fused_kernel(const float* __restrict__ sentence,
             const float* __restrict__ Wf, const float* __restrict__ bf,
             const float* __restrict__ Wi, const float* __restrict__ bi,
             const float* __restrict__ Wu, const float* __restrict__ bu,
             const float* __restrict__ Wo, const float* __restrict__ bo,
             const float* __restrict__ thf, const float* __restrict__ thi,
             const float* __restrict__ thu, const float* __restrict__ tho) {
    if (blockIdx.x < NCHUNK) {
        if (threadIdx.x < 32)
            qlstm_scan(blockIdx.x, Wf, bf, Wi, bi, Wu, bu, Wo, bo,
                       thf, thi, thu, tho);
        return;
    }

    // producer block
    __shared__ float tc[63], ts[63];
    const int tid = threadIdx.x;
    if (tid < 63) { tc[tid] = g_trig[2 * tid]; ts[tid] = g_trig[2 * tid + 1]; }
    __syncthreads();

    const int lane = tid & 31;
    const int wid  = tid >> 5;
    for (int s = (blockIdx.x - NCHUNK) * 8 + wid; s < SEQN; s += PSTRIDE)
        qcnn_warp(sentence, s, tc, ts, lane);
}

// ============================================================
// Head: logits + log_softmax. One warp per timestep row.
// ============================================================
__global__ void head_kernel(const float* __restrict__ Wt, const float* __restrict__ bt,
                            float* __restrict__ out) {
    const int warp = (blockIdx.x * blockDim.x + threadIdx.x) >> 5;
    const int lane = threadIdx.x & 31;
    if (warp >= SEQN) return;

    float h0 = g_hs[warp * 4 + 0];
    float h1 = g_hs[warp * 4 + 1];
    float h2 = g_hs[warp * 4 + 2];
    float h3 = g_hs[warp * 4 + 3];

    float l = bt[lane];
    l = fmaf(h0, Wt[lane * 4 + 0], l);
    l = fmaf(h1, Wt[lane * 4 + 1], l);
    l = fmaf(h2, Wt[lane * 4 + 2], l);
    l = fmaf(h3, Wt[lane * 4 + 3], l);

    float m = l;
#pragma unroll
    for (int o = 16; o; o >>= 1) m = fmaxf(m, __shfl_xor_sync(FULLM, m, o));
    float e = __expf(l - m);
    float sum = e;
#pragma unroll
    for (int o = 16; o; o >>= 1) sum += __shfl_xor_sync(FULLM, sum, o);

    out[warp * 32 + lane] = (l - m) - __logf(sum);
}

// ============================================================
extern "C" void kernel_launch(void* const* d_in, const int* in_sizes, int n_in,
                              void* d_out, int out_size) {
    const float* sentence = (const float*)d_in[0];
    const float* qcnn_w   = (const float*)d_in[1];
    const float* Wf  = (const float*)d_in[2];
    const float* bf  = (const float*)d_in[3];
    const float* Wi  = (const float*)d_in[4];
    const float* bi  = (const float*)d_in[5];
    const float* Wu  = (const float*)d_in[6];
    const float* bu  = (const float*)d_in[7];
    const float* Wo  = (const float*)d_in[8];
    const float* bo  = (const float*)d_in[9];
    const float* thf = (const float*)d_in[10];
    const float* thi = (const float*)d_in[11];
    const float* thu = (const float*)d_in[12];
    const float* tho = (const float*)d_in[13];
    const float* Wt  = (const float*)d_in[14];
    const float* bt  = (const float*)d_in[15];
    float* out = (float*)d_out;

    prep_kernel<<<1, 256>>>(qcnn_w);
    fused_kernel<<<NBLK, 256>>>(sentence,
                                Wf, bf, Wi, bi, Wu, bu, Wo, bo,
                                thf, thi, thu, tho);
    head_kernel<<<(SEQN * 32) / 256, 256>>>(Wt, bt, out);
}

// round 6
// speedup vs baseline: 19.0205x; 1.0366x over previous
#include <cuda_runtime.h>
#include <math.h>

#define SEQN 2048
#define PF 16
#define NBLK 148            // #SMs; blocks 0..15 = scan (4 warps = 4 chunks each), 16..147 producers
#define NCHUNK 64
#define CH_LEN 32           // SEQN / NCHUNK
#define WARM 48             // warm-up steps (0.731^48 ~ 3e-7)
#define NSCANBLK 16
#define NPB (NBLK - NSCANBLK)  // 132 producer blocks
#define PSTRIDE (NPB * 8)      // samples per sweep (8 warps/block)

#define NOT_READY -1.0e30f
#define QBIAS 10.0f
#define FULLM 0xFFFFFFFFu
#define RTC 0.70710678118654752440f

// ---- device scratch (no allocations allowed) ----
__device__ float g_trig[2 * 63];            // cos,sin of w[j]/2
__device__ volatile float g_q[SEQN + PF];   // data+flag channel: ready iff > 5

// ============================================================
// Kernel 1: trig precompute + q-channel sentinel init (+padding)
// ============================================================
__global__ void prep_kernel(const float* __restrict__ w) {
    int j = threadIdx.x;
    if (j < 63) {
        float s, c;
        sincosf(0.5f * w[j], &s, &c);
        g_trig[2 * j]     = c;
        g_trig[2 * j + 1] = s;
    }
    for (int i = j; i < SEQN + PF; i += blockDim.x)
        g_q[i] = (i < SEQN) ? NOT_READY : QBIAS;   // padding pre-ready
}

// ============================================================
// Warp-per-sample QCNN: 256 amplitudes, 8 per lane in registers.
// amp index = (lane << 3) | j : qubits 0-2 = j bits (in-register),
// qubits 3-7 = lane bits (shfl.xor). No __syncthreads anywhere.
// ============================================================
template<int Q>
__device__ __forceinline__ void RZg(float (&ar)[8], float (&ai)[8],
                                    float c, float s, int lane) {
#pragma unroll
    for (int j = 0; j < 8; j++) {
        int b = (Q < 3) ? ((j >> Q) & 1) : ((lane >> (Q - 3)) & 1);
        float ss = b ? s : -s;
        float nr = ar[j] * c - ai[j] * ss;
        ai[j] = fmaf(ar[j], ss, ai[j] * c);
        ar[j] = nr;
    }
}

template<int Q>
__device__ __forceinline__ void PHg(float (&ar)[8], float (&ai)[8],
                                    float c, float s, int lane) {
#pragma unroll
    for (int j = 0; j < 8; j++) {
        int b = (Q < 3) ? ((j >> Q) & 1) : ((lane >> (Q - 3)) & 1);
        float cc = b ? c : 1.0f;
        float ss = b ? s : 0.0f;
        float nr = ar[j] * cc - ai[j] * ss;
        ai[j] = fmaf(ar[j], ss, ai[j] * cc);
        ar[j] = nr;
    }
}

template<int Q>
__device__ __forceinline__ void Hg(float (&ar)[8], float (&ai)[8], int lane) {
    if (Q < 3) {
#pragma unroll
        for (int j = 0; j < 8; j++)
            if (((j >> Q) & 1) == 0) {
                int j1 = j | (1 << Q);
                float r0 = ar[j], r1 = ar[j1], i0 = ai[j], i1 = ai[j1];
                ar[j]  = (r0 + r1) * RTC;  ar[j1] = (r0 - r1) * RTC;
                ai[j]  = (i0 + i1) * RTC;  ai[j1] = (i0 - i1) * RTC;
            }
    } else {
        const int m = 1 << (Q - 3);
        float sgn = ((lane >> (Q - 3)) & 1) ? -1.0f : 1.0f;
#pragma unroll
        for (int j = 0; j < 8; j++) {
            float orr = __shfl_xor_sync(FULLM, ar[j], m);
            float oii = __shfl_xor_sync(FULLM, ai[j], m);
            ar[j] = fmaf(sgn, ar[j], orr) * RTC;
            ai[j] = fmaf(sgn, ai[j], oii) * RTC;
        }
    }
}

template<int Q>
__device__ __forceinline__ void RYg(float (&ar)[8], float (&ai)[8],
                                    float c, float s, int lane) {
    if (Q < 3) {
#pragma unroll
        for (int j = 0; j < 8; j++)
            if (((j >> Q) & 1) == 0) {
                int j1 = j | (1 << Q);
                float r0 = ar[j], r1 = ar[j1], i0 = ai[j], i1 = ai[j1];
                ar[j]  = fmaf(c, r0, -s * r1);  ar[j1] = fmaf(s, r0, c * r1);
                ai[j]  = fmaf(c, i0, -s * i1);  ai[j1] = fmaf(s, i0, c * i1);
            }
    } else {
        const int m = 1 << (Q - 3);
        float ss = ((lane >> (Q - 3)) & 1) ? s : -s;
#pragma unroll
        for (int j = 0; j < 8; j++) {
            float orr = __shfl_xor_sync(FULLM, ar[j], m);
            float oii = __shfl_xor_sync(FULLM, ai[j], m);
            ar[j] = fmaf(c, ar[j], ss * orr);
            ai[j] = fmaf(c, ai[j], ss * oii);
        }
    }
}

template<int CQ, int TQ>
__device__ __forceinline__ void CXg(float (&ar)[8], float (&ai)[8], int lane) {
    if (CQ < 3 && TQ < 3) {
#pragma unroll
        for (int j = 0; j < 8; j++)
            if ((((j >> CQ) & 1) == 1) && (((j >> TQ) & 1) == 0)) {
                int j1 = j | (1 << TQ);
                float tr = ar[j]; ar[j] = ar[j1]; ar[j1] = tr;
                float ti = ai[j]; ai[j] = ai[j1]; ai[j1] = ti;
            }
    } else if (CQ < 3) {              // target cross-lane
        const int m = 1 << (TQ - 3);
#pragma unroll
        for (int j = 0; j < 8; j++)
            if (((j >> CQ) & 1) == 1) {
                ar[j] = __shfl_xor_sync(FULLM, ar[j], m);
                ai[j] = __shfl_xor_sync(FULLM, ai[j], m);
            }
    } else if (TQ < 3) {              // control in lane, target local
        int b = (lane >> (CQ - 3)) & 1;
#pragma unroll
        for (int j = 0; j < 8; j++)
            if (((j >> TQ) & 1) == 0) {
                int j1 = j | (1 << TQ);
                float r0 = ar[j], r1 = ar[j1];
                ar[j] = b ? r1 : r0;  ar[j1] = b ? r0 : r1;
                float i0 = ai[j], i1 = ai[j1];
                ai[j] = b ? i1 : i0;  ai[j1] = b ? i0 : i1;
            }
    } else {                          // both cross-lane
        const int m = 1 << (TQ - 3);
        int b = (lane >> (CQ - 3)) & 1;
#pragma unroll
        for (int j = 0; j < 8; j++) {
            float orr = __shfl_xor_sync(FULLM, ar[j], m);
            float oii = __shfl_xor_sync(FULLM, ai[j], m);
            ar[j] = b ? orr : ar[j];
            ai[j] = b ? oii : ai[j];
        }
    }
}

template<int A, int B>
__device__ __forceinline__ void conv_t(float (&ar)[8], float (&ai)[8],
                                       const float* tc, const float* ts,
                                       int k, int lane) {
    RZg<B>(ar, ai, RTC, -RTC, lane);
    CXg<B, A>(ar, ai, lane);
    RZg<A>(ar, ai, tc[k], ts[k], lane);
    RYg<B>(ar, ai, tc[k + 1], ts[k + 1], lane);
    CXg<A, B>(ar, ai, lane);
    RYg<B>(ar, ai, tc[k + 2], ts[k + 2], lane);
    CXg<B, A>(ar, ai, lane);
    RZg<A>(ar, ai, RTC, RTC, lane);
}

template<int A, int B>
__device__ __forceinline__ void pool_t(float (&ar)[8], float (&ai)[8],
                                       const float* tc, const float* ts,
                                       int k, int lane) {
    RZg<B>(ar, ai, RTC, -RTC, lane);
    CXg<B, A>(ar, ai, lane);
    RZg<A>(ar, ai, tc[k], ts[k], lane);
    RYg<B>(ar, ai, tc[k + 1], ts[k + 1], lane);
    CXg<A, B>(ar, ai, lane);
    RYg<B>(ar, ai, tc[k + 2], ts[k + 2], lane);
}

__device__ void qcnn_warp(const float* __restrict__ sentence, int s,
                          const float* tc, const float* ts, int lane) {
    float ar[8], ai[8];
#pragma unroll
    for (int j = 0; j < 8; j++) { ar[j] = 0.0f; ai[j] = 0.0f; }
    if (lane == 0) ar[0] = 1.0f;

    float myC = 1.0f, myS = 0.0f;
    if (lane < 8) {
        float x = sentence[s * 8 + lane];
        sincosf(2.0f * x, &myS, &myC);
    }

#define FM(Q) { Hg<Q>(ar, ai, lane); \
                float pc = __shfl_sync(FULLM, myC, Q); \
                float ps = __shfl_sync(FULLM, myS, Q); \
                PHg<Q>(ar, ai, pc, ps, lane); }
    FM(0) FM(1) FM(2) FM(3) FM(4) FM(5) FM(6) FM(7)
#undef FM

    conv_t<0, 1>(ar, ai, tc, ts, 0, lane);
    conv_t<2, 3>(ar, ai, tc, ts, 3, lane);
    conv_t<4, 5>(ar, ai, tc, ts, 6, lane);
    conv_t<6, 7>(ar, ai, tc, ts, 9, lane);
    conv_t<1, 2>(ar, ai, tc, ts, 12, lane);
    conv_t<3, 4>(ar, ai, tc, ts, 15, lane);
    conv_t<5, 6>(ar, ai, tc, ts, 18, lane);
    conv_t<7, 0>(ar, ai, tc, ts, 21, lane);
    pool_t<0, 4>(ar, ai, tc, ts, 24, lane);
    pool_t<1, 5>(ar, ai, tc, ts, 27, lane);
    pool_t<2, 6>(ar, ai, tc, ts, 30, lane);
    pool_t<3, 7>(ar, ai, tc, ts, 33, lane);
    conv_t<0, 1>(ar, ai, tc, ts, 36, lane);
    conv_t<2, 3>(ar, ai, tc, ts, 39, lane);
    conv_t<1, 2>(ar, ai, tc, ts, 42, lane);
    conv_t<3, 0>(ar, ai, tc, ts, 45, lane);
    pool_t<0, 2>(ar, ai, tc, ts, 48, lane);
    pool_t<1, 3>(ar, ai, tc, ts, 51, lane);
    conv_t<0, 1>(ar, ai, tc, ts, 54, lane);
    conv_t<1, 0>(ar, ai, tc, ts, 57, lane);
    pool_t<0, 1>(ar, ai, tc, ts, 60, lane);

    float v = 0.0f;
#pragma unroll
    for (int j = 0; j < 8; j++) v += ar[j] * ar[j] + ai[j] * ai[j];
    if ((lane >> 4) & 1) v = -v;               // Z on qubit 7 = lane bit 4
#pragma unroll
    for (int o = 16; o; o >>= 1) v += __shfl_xor_sync(FULLM, v, o);
    if (lane == 0) g_q[s] = v + QBIAS;         // single-word data+flag
}

// ============================================================
// Runtime poly fits: tanh(x) ~= x * P(x^2), Chebyshev-node Newton
// interpolation of g(v)=tanh(sqrt v)/sqrt v.
// ============================================================
__device__ __forceinline__ void fit_g8(float vmax, float* C) {   // deg-7 in v
    const float cs0 = 0.98078528f, cs1 = 0.83146961f,
                cs2 = 0.55557023f, cs3 = 0.19509032f;
    float v[8], d[8];
    v[0] = 0.5f * vmax * (1.0f + cs0);
    v[1] = 0.5f * vmax * (1.0f + cs1);
    v[2] = 0.5f * vmax * (1.0f + cs2);
    v[3] = 0.5f * vmax * (1.0f + cs3);
    v[4] = 0.5f * vmax * (1.0f - cs3);
    v[5] = 0.5f * vmax * (1.0f - cs2);
    v[6] = 0.5f * vmax * (1.0f - cs1);
    v[7] = 0.5f * vmax * (1.0f - cs0);
#pragma unroll
    for (int k = 0; k < 8; k++) {
        float x = sqrtf(v[k]);
        d[k] = tanhf(x) / x;
    }
#pragma unroll
    for (int j = 1; j < 8; j++)
#pragma unroll
        for (int k = 7; k >= 1; k--)
            if (k >= j) d[k] = (d[k] - d[k - 1]) / (v[k] - v[k - j]);
#pragma unroll
    for (int i = 0; i < 8; i++) C[i] = 0.0f;
    C[0] = d[7];
#pragma unroll
    for (int k = 6; k >= 0; k--) {
#pragma unroll
        for (int i = 7; i >= 1; i--) C[i] = C[i - 1] - v[k] * C[i];
        C[0] = d[k] - v[k] * C[0];
    }
}

__device__ __forceinline__ void fit_g6(float vmax, float* C) {   // deg-5 in v
    const float cs0 = 0.96592583f, cs1 = 0.70710678f, cs2 = 0.25881905f;
    float v[6], d[6];
    v[0] = 0.5f * vmax * (1.0f + cs0);
    v[1] = 0.5f * vmax * (1.0f + cs1);
    v[2] = 0.5f * vmax * (1.0f + cs2);
    v[3] = 0.5f * vmax * (1.0f - cs2);
    v[4] = 0.5f * vmax * (1.0f - cs1);
    v[5] = 0.5f * vmax * (1.0f - cs0);
#pragma unroll
    for (int k = 0; k < 6; k++) {
        float x = sqrtf(v[k]);
        d[k] = tanhf(x) / x;
    }
#pragma unroll
    for (int j = 1; j < 6; j++)
#pragma unroll
        for (int k = 5; k >= 1; k--)
            if (k >= j) d[k] = (d[k] - d[k - 1]) / (v[k] - v[k - j]);
#pragma unroll
    for (int i = 0; i < 6; i++) C[i] = 0.0f;
    C[0] = d[5];
#pragma unroll
    for (int k = 4; k >= 0; k--) {
#pragma unroll
        for (int i = 5; i >= 1; i--) C[i] = C[i - 1] - v[k] * C[i];
        C[0] = d[k] - v[k] * C[0];
    }
}

__device__ __forceinline__ float estrin8(const float* K, float u) {
    float u2 = u * u;
    float u4 = u2 * u2;
    float a = fmaf(K[1], u, K[0]);
    float b = fmaf(K[3], u, K[2]);
    float c = fmaf(K[5], u, K[4]);
    float d = fmaf(K[7], u, K[6]);
    float ab = fmaf(b, u2, a);
    float cd = fmaf(d, u2, c);
    return fmaf(cd, u4, ab);
}

__device__ __forceinline__ float estrin6(const float* K, float u) {
    float u2 = u * u;
    float u4 = u2 * u2;
    float a = fmaf(K[1], u, K[0]);
    float b = fmaf(K[3], u, K[2]);
    float c = fmaf(K[5], u, K[4]);
    float ab = fmaf(b, u2, a);
    return fmaf(c, u4, ab);
}

// ============================================================
// Chunked QLSTM scan, lane=gate layout (one warp per chunk).
// Lane g computes y/cos/z/act for ALL 4 wires of its gate
// (z products use only same-gate cosines -> no shuffle), then ONE
// gather round (acts across gates), then every lane redundantly
// computes c_q, h_q for all wires -> no h broadcast round.
// After the scan, the same warp computes logits+log_softmax for its
// CH_LEN rows (lane = tag) from block-shared h.
// ============================================================
__device__ void qlstm_scan(int chunk,
                           const float* __restrict__ Wf, const float* __restrict__ bf,
                           const float* __restrict__ Wi, const float* __restrict__ bi,
                           const float* __restrict__ Wu, const float* __restrict__ bu,
                           const float* __restrict__ Wo, const float* __restrict__ bo,
                           const float* __restrict__ thf, const float* __restrict__ thi,
                           const float* __restrict__ thu, const float* __restrict__ tho,
                           const float* __restrict__ Wt, const float* __restrict__ bt,
                           float* __restrict__ out, float4* hsrow) {
    const int l = threadIdx.x & 31;
    const int g = l & 3;
    const int base = l & ~3;

    const int begin = chunk * CH_LEN;
    const int warm0raw = begin - WARM;
    const int warm0 = (warm0raw < 0) ? 0 : warm0raw;
    const int end = begin + CH_LEN;

    const float* W  = (g == 0) ? Wf  : (g == 1) ? Wi  : (g == 2) ? Wu  : Wo;
    const float* b  = (g == 0) ? bf  : (g == 1) ? bi  : (g == 2) ? bu  : bo;
    const float* th = (g == 0) ? thf : (g == 1) ? thi : (g == 2) ? thu : tho;

    float w0[4], w1[4], w2[4], w3[4], w4[4], ub[4];
#pragma unroll
    for (int qq = 0; qq < 4; qq++) {
        w0[qq] = W[qq * 5 + 0];
        w1[qq] = W[qq * 5 + 1];
        w2[qq] = W[qq * 5 + 2];
        w3[qq] = W[qq * 5 + 3];
        w4[qq] = W[qq * 5 + 4];
        ub[qq] = b[qq] + th[qq];
    }

    const bool isU = (g == 2);

    float gA[6], gB[8];
    fit_g6(1.0f, gA);     // tanh on [-1,1] (deg-11 odd)
    fit_g8(4.35f, gB);    // tanh on [-2.085,2.085] (|c| <= 2.071)

    // per-lane act coeffs: u-lane tanh(z)=z*gA(z^2);
    // sigma lanes: 0.5 + z*0.25*gA(z^2/4) -> fold 4^-j into coeffs
    float aK[6];
    {
        float s = 0.25f;
#pragma unroll
        for (int j = 0; j < 6; j++) {
            aK[j] = isU ? gA[j] : gA[j] * s;
            s *= 0.25f;
        }
    }
    const float Kc = isU ? 0.0f : 0.5f;

    // prologue: wait for first PF window
    float nq[PF];
    {
        float mn;
        do {
            mn = 1e30f;
#pragma unroll
            for (int j = 0; j < PF; j++) {
                float x = g_q[warm0 + j];
                nq[j] = x;
                mn = fminf(mn, x);
            }
        } while (mn < 5.0f);
    }

    float c0s = 0.0f, c1s = 0.0f, c2s = 0.0f, c3s = 0.0f;
    float h0 = 0.0f, h1 = 0.0f, h2 = 0.0f, h3 = 0.0f;

    for (int t0 = warm0; t0 < end; t0 += PF) {
        const bool wr = (l == 0) && (t0 >= begin);
        float pn[PF];
#pragma unroll
        for (int j = 0; j < PF; j++) pn[j] = g_q[t0 + PF + j];   // prefetch

#pragma unroll
        for (int j = 0; j < PF; j++) {
            const int t = t0 + j;
            const float qv = nq[j] - QBIAS;

            // y_q = ub + W0 q + w.h   (4 wires, this gate)
            float y0 = fmaf(w2[0], h1, fmaf(w1[0], h0, fmaf(w0[0], qv, ub[0])))
                     + fmaf(w4[0], h3, w3[0] * h2);
            float y1 = fmaf(w2[1], h1, fmaf(w1[1], h0, fmaf(w0[1], qv, ub[1])))
                     + fmaf(w4[1], h3, w3[1] * h2);
            float y2 = fmaf(w2[2], h1, fmaf(w1[2], h0, fmaf(w0[2], qv, ub[2])))
                     + fmaf(w4[2], h3, w3[2] * h2);
            float y3 = fmaf(w2[3], h1, fmaf(w1[3], h0, fmaf(w0[3], qv, ub[3])))
                     + fmaf(w4[3], h3, w3[3] * h2);

            const float cz0 = __cosf(y0);
            const float cz1 = __cosf(y1);
            const float cz2 = __cosf(y2);
            const float cz3 = __cosf(y3);

            // z products (same gate, local): z0=c1c2c3, z1=c0c1, z2=z1c2, z3=z2c3
            const float t23 = cz2 * cz3;
            const float z0 = cz1 * t23;
            const float z1 = cz0 * cz1;
            const float z2 = z1 * cz2;
            const float z3 = z2 * cz3;

            // activation (per-lane type) for all 4 wires
            const float a0 = fmaf(z0, estrin6(aK, z0 * z0), Kc);
            const float a1 = fmaf(z1, estrin6(aK, z1 * z1), Kc);
            const float a2 = fmaf(z2, estrin6(aK, z2 * z2), Kc);
            const float a3 = fmaf(z3, estrin6(aK, z3 * z3), Kc);

            // ONE gather round: acts of all 4 gates (within lane group of 4)
            const float f0 = __shfl_sync(FULLM, a0, base + 0);
            const float f1 = __shfl_sync(FULLM, a1, base + 0);
            const float f2 = __shfl_sync(FULLM, a2, base + 0);
            const float f3 = __shfl_sync(FULLM, a3, base + 0);
            const float i0 = __shfl_sync(FULLM, a0, base + 1);
            const float i1 = __shfl_sync(FULLM, a1, base + 1);
            const float i2 = __shfl_sync(FULLM, a2, base + 1);
            const float i3 = __shfl_sync(FULLM, a3, base + 1);
            const float u0 = __shfl_sync(FULLM, a0, base + 2);
            const float u1 = __shfl_sync(FULLM, a1, base + 2);
            const float u2 = __shfl_sync(FULLM, a2, base + 2);
            const float u3 = __shfl_sync(FULLM, a3, base + 2);
            const float o0 = __shfl_sync(FULLM, a0, base + 3);
            const float o1 = __shfl_sync(FULLM, a1, base + 3);
            const float o2 = __shfl_sync(FULLM, a2, base + 3);
            const float o3 = __shfl_sync(FULLM, a3, base + 3);

            // cell update + h (replicated across lanes)
            c0s = fmaf(f0, c0s, i0 * u0);
            c1s = fmaf(f1, c1s, i1 * u1);
            c2s = fmaf(f2, c2s, i2 * u2);
            c3s = fmaf(f3, c3s, i3 * u3);

            h0 = (o0 * c0s) * estrin8(gB, c0s * c0s);
            h1 = (o1 * c1s) * estrin8(gB, c1s * c1s);
            h2 = (o2 * c2s) * estrin8(gB, c2s * c2s);
            h3 = (o3 * c3s) * estrin8(gB, c3s * c3s);

            if (wr) hsrow[t - begin] = make_float4(h0, h1, h2, h3);
        }

        // verify prefetched window; spin only if producer behind
        float mn = pn[0];
#pragma unroll
        for (int j = 1; j < PF; j++) mn = fminf(mn, pn[j]);
        while (mn < 5.0f) {
            mn = 1e30f;
#pragma unroll
            for (int j = 0; j < PF; j++) {
                float x = g_q[t0 + PF + j];
                pn[j] = x;
                mn = fminf(mn, x);
            }
        }
#pragma unroll
        for (int j = 0; j < PF; j++) nq[j] = pn[j];
    }

    // -------- head epilogue: lane = tag, rows = this chunk --------
    __syncwarp();
    const float wt0 = Wt[l * 4 + 0];
    const float wt1 = Wt[l * 4 + 1];
    const float wt2 = Wt[l * 4 + 2];
    const float wt3 = Wt[l * 4 + 3];
    const float btv = bt[l];

    for (int r = 0; r < CH_LEN; r++) {
        float4 h = hsrow[r];
        float lg = btv;
        lg = fmaf(h.x, wt0, lg);
        lg = fmaf(h.y, wt1, lg);
        lg = fmaf(h.z, wt2, lg);
        lg = fmaf(h.w, wt3, lg);

        float m = lg;
#pragma unroll
        for (int o = 16; o; o >>= 1) m = fmaxf(m, __shfl_xor_sync(FULLM, m, o));
        float e = __expf(lg - m);
        float sum = e;
#pragma unroll
        for (int o = 16; o; o >>= 1) sum += __shfl_xor_sync(FULLM, sum, o);

        out[(begin + r) * 32 + l] = (lg - m) - __logf(sum);
    }
}

// ============================================================
// Fused kernel: 148 blocks (1/SM). Blocks 0..15 = scan (4 warps
// = 4 chunks each, incl. head epilogue); blocks 16..147 = producers.
// ============================================================
__global__ void __launch_bounds__(256, 1)
fused_kernel(const float* __restrict__ sentence,
             const float* __restrict__ Wf, const float* __restrict__ bf,
             const float* __restrict__ Wi, const float* __restrict__ bi,
             const float* __restrict__ Wu, const float* __restrict__ bu,
             const float* __restrict__ Wo, const float* __restrict__ bo,
             const float* __restrict__ thf, const float* __restrict__ thi,
             const float* __restrict__ thu, const float* __restrict__ tho,
             const float* __restrict__ Wt, const float* __restrict__ bt,
             float* __restrict__ out) {
    if (blockIdx.x < NSCANBLK) {
        __shared__ float4 hbuf[4][CH_LEN];
        const int w = threadIdx.x >> 5;
        if (threadIdx.x < 128)
            qlstm_scan(blockIdx.x * 4 + w,
                       Wf, bf, Wi, bi, Wu, bu, Wo, bo,
                       thf, thi, thu, tho, Wt, bt, out, hbuf[w]);
        return;
    }

    // producer block
    __shared__ float tc[63], ts[63];
    const int tid = threadIdx.x;
    if (tid < 63) { tc[tid] = g_trig[2 * tid]; ts[tid] = g_trig[2 * tid + 1]; }
    __syncthreads();

    const int lane = tid & 31;
    const int wid  = tid >> 5;
    for (int s = (blockIdx.x - NSCANBLK) * 8 + wid; s < SEQN; s += PSTRIDE)
        qcnn_warp(sentence, s, tc, ts, lane);
}

// ============================================================
extern "C" void kernel_launch(void* const* d_in, const int* in_sizes, int n_in,
                              void* d_out, int out_size) {
    const float* sentence = (const float*)d_in[0];
    const float* qcnn_w   = (const float*)d_in[1];
    const float* Wf  = (const float*)d_in[2];
    const float* bf  = (const float*)d_in[3];
    const float* Wi  = (const float*)d_in[4];
    const float* bi  = (const float*)d_in[5];
    const float* Wu  = (const float*)d_in[6];
    const float* bu  = (const float*)d_in[7];
    const float* Wo  = (const float*)d_in[8];
    const float* bo  = (const float*)d_in[9];
    const float* thf = (const float*)d_in[10];
    const float* thi = (const float*)d_in[11];
    const float* thu = (const float*)d_in[12];
    const float* tho = (const float*)d_in[13];
    const float* Wt  = (const float*)d_in[14];
    const float* bt  = (const float*)d_in[15];
    float* out = (float*)d_out;

    prep_kernel<<<1, 256>>>(qcnn_w);
    fused_kernel<<<NBLK, 256>>>(sentence,
                                Wf, bf, Wi, bi, Wu, bu, Wo, bo,
                                thf, thi, thu, tho, Wt, bt, out);
}

// round 7
// speedup vs baseline: 25.7946x; 1.3562x over previous
#include <cuda_runtime.h>
#include <math.h>

#define SEQN 2048
#define PF 8
#define NBLK 148            // #SMs; blocks 0..15 = scan, 16..147 = producers
#define NCHUNK 64
#define CH_LEN 32           // SEQN / NCHUNK
#define WARM 40             // warm-up steps (0.731^40 ~ 3.6e-6)
#define NSCANBLK 16
#define NPB (NBLK - NSCANBLK)  // 132 producer blocks x 16 warps = 2112 >= 2048

#define NOT_READY -1.0e30f
#define QBIAS 10.0f
#define FULLM 0xFFFFFFFFu
#define RTC 0.70710678118654752440f

// ---- device scratch (no allocations allowed) ----
__device__ float g_trig[2 * 63];            // cos,sin of w[j]/2
__device__ volatile float g_q[SEQN + PF];   // data+flag channel: ready iff > 5

// ============================================================
// Kernel 1: trig precompute + q-channel sentinel init (+padding)
// ============================================================
__global__ void prep_kernel(const float* __restrict__ w) {
    int j = blockIdx.x * blockDim.x + threadIdx.x;
    if (blockIdx.x == 0 && threadIdx.x < 63) {
        float s, c;
        sincosf(0.5f * w[threadIdx.x], &s, &c);
        g_trig[2 * threadIdx.x]     = c;
        g_trig[2 * threadIdx.x + 1] = s;
    }
    for (int i = j; i < SEQN + PF; i += gridDim.x * blockDim.x)
        g_q[i] = (i < SEQN) ? NOT_READY : QBIAS;   // padding pre-ready
}

// ============================================================
// Warp-per-sample QCNN: 256 amplitudes, 8 per lane in registers.
// amp index = (lane << 3) | j : qubits 0-2 = j bits (in-register),
// qubits 3-7 = lane bits (shfl.xor). No __syncthreads anywhere.
// ============================================================
template<int Q>
__device__ __forceinline__ void RZg(float (&ar)[8], float (&ai)[8],
                                    float c, float s, int lane) {
#pragma unroll
    for (int j = 0; j < 8; j++) {
        int b = (Q < 3) ? ((j >> Q) & 1) : ((lane >> (Q - 3)) & 1);
        float ss = b ? s : -s;
        float nr = ar[j] * c - ai[j] * ss;
        ai[j] = fmaf(ar[j], ss, ai[j] * c);
        ar[j] = nr;
    }
}

template<int Q>
__device__ __forceinline__ void PHg(float (&ar)[8], float (&ai)[8],
                                    float c, float s, int lane) {
#pragma unroll
    for (int j = 0; j < 8; j++) {
        int b = (Q < 3) ? ((j >> Q) & 1) : ((lane >> (Q - 3)) & 1);
        float cc = b ? c : 1.0f;
        float ss = b ? s : 0.0f;
        float nr = ar[j] * cc - ai[j] * ss;
        ai[j] = fmaf(ar[j], ss, ai[j] * cc);
        ar[j] = nr;
    }
}

template<int Q>
__device__ __forceinline__ void Hg(float (&ar)[8], float (&ai)[8], int lane) {
    if (Q < 3) {
#pragma unroll
        for (int j = 0; j < 8; j++)
            if (((j >> Q) & 1) == 0) {
                int j1 = j | (1 << Q);
                float r0 = ar[j], r1 = ar[j1], i0 = ai[j], i1 = ai[j1];
                ar[j]  = (r0 + r1) * RTC;  ar[j1] = (r0 - r1) * RTC;
                ai[j]  = (i0 + i1) * RTC;  ai[j1] = (i0 - i1) * RTC;
            }
    } else {
        const int m = 1 << (Q - 3);
        float sgn = ((lane >> (Q - 3)) & 1) ? -1.0f : 1.0f;
#pragma unroll
        for (int j = 0; j < 8; j++) {
            float orr = __shfl_xor_sync(FULLM, ar[j], m);
            float oii = __shfl_xor_sync(FULLM, ai[j], m);
            ar[j] = fmaf(sgn, ar[j], orr) * RTC;
            ai[j] = fmaf(sgn, ai[j], oii) * RTC;
        }
    }
}

template<int Q>
__device__ __forceinline__ void RYg(float (&ar)[8], float (&ai)[8],
                                    float c, float s, int lane) {
    if (Q < 3) {
#pragma unroll
        for (int j = 0; j < 8; j++)
            if (((j >> Q) & 1) == 0) {
                int j1 = j | (1 << Q);
                float r0 = ar[j], r1 = ar[j1], i0 = ai[j], i1 = ai[j1];
                ar[j]  = fmaf(c, r0, -s * r1);  ar[j1] = fmaf(s, r0, c * r1);
                ai[j]  = fmaf(c, i0, -s * i1);  ai[j1] = fmaf(s, i0, c * i1);
            }
    } else {
        const int m = 1 << (Q - 3);
        float ss = ((lane >> (Q - 3)) & 1) ? s : -s;
#pragma unroll
        for (int j = 0; j < 8; j++) {
            float orr = __shfl_xor_sync(FULLM, ar[j], m);
            float oii = __shfl_xor_sync(FULLM, ai[j], m);
            ar[j] = fmaf(c, ar[j], ss * orr);
            ai[j] = fmaf(c, ai[j], ss * oii);
        }
    }
}

template<int CQ, int TQ>
__device__ __forceinline__ void CXg(float (&ar)[8], float (&ai)[8], int lane) {
    if (CQ < 3 && TQ < 3) {
#pragma unroll
        for (int j = 0; j < 8; j++)
            if ((((j >> CQ) & 1) == 1) && (((j >> TQ) & 1) == 0)) {
                int j1 = j | (1 << TQ);
                float tr = ar[j]; ar[j] = ar[j1]; ar[j1] = tr;
                float ti = ai[j]; ai[j] = ai[j1]; ai[j1] = ti;
            }
    } else if (CQ < 3) {              // target cross-lane
        const int m = 1 << (TQ - 3);
#pragma unroll
        for (int j = 0; j < 8; j++)
            if (((j >> CQ) & 1) == 1) {
                ar[j] = __shfl_xor_sync(FULLM, ar[j], m);
                ai[j] = __shfl_xor_sync(FULLM, ai[j], m);
            }
    } else if (TQ < 3) {              // control in lane, target local
        int b = (lane >> (CQ - 3)) & 1;
#pragma unroll
        for (int j = 0; j < 8; j++)
            if (((j >> TQ) & 1) == 0) {
                int j1 = j | (1 << TQ);
                float r0 = ar[j], r1 = ar[j1];
                ar[j] = b ? r1 : r0;  ar[j1] = b ? r0 : r1;
                float i0 = ai[j], i1 = ai[j1];
                ai[j] = b ? i1 : i0;  ai[j1] = b ? i0 : i1;
            }
    } else {                          // both cross-lane
        const int m = 1 << (TQ - 3);
        int b = (lane >> (CQ - 3)) & 1;
#pragma unroll
        for (int j = 0; j < 8; j++) {
            float orr = __shfl_xor_sync(FULLM, ar[j], m);
            float oii = __shfl_xor_sync(FULLM, ai[j], m);
            ar[j] = b ? orr : ar[j];
            ai[j] = b ? oii : ai[j];
        }
    }
}

template<int A, int B>
__device__ __forceinline__ void conv_t(float (&ar)[8], float (&ai)[8],
                                       const float* tc, const float* ts,
                                       int k, int lane) {
    RZg<B>(ar, ai, RTC, -RTC, lane);
    CXg<B, A>(ar, ai, lane);
    RZg<A>(ar, ai, tc[k], ts[k], lane);
    RYg<B>(ar, ai, tc[k + 1], ts[k + 1], lane);
    CXg<A, B>(ar, ai, lane);
    RYg<B>(ar, ai, tc[k + 2], ts[k + 2], lane);
    CXg<B, A>(ar, ai, lane);
    RZg<A>(ar, ai, RTC, RTC, lane);
}

template<int A, int B>
__device__ __forceinline__ void pool_t(float (&ar)[8], float (&ai)[8],
                                       const float* tc, const float* ts,
                                       int k, int lane) {
    RZg<B>(ar, ai, RTC, -RTC, lane);
    CXg<B, A>(ar, ai, lane);
    RZg<A>(ar, ai, tc[k], ts[k], lane);
    RYg<B>(ar, ai, tc[k + 1], ts[k + 1], lane);
    CXg<A, B>(ar, ai, lane);
    RYg<B>(ar, ai, tc[k + 2], ts[k + 2], lane);
}

__device__ void qcnn_warp(const float* __restrict__ sentence, int s,
                          const float* tc, const float* ts, int lane) {
    float ar[8], ai[8];
#pragma unroll
    for (int j = 0; j < 8; j++) { ar[j] = 0.0f; ai[j] = 0.0f; }
    if (lane == 0) ar[0] = 1.0f;

    float myC = 1.0f, myS = 0.0f;
    if (lane < 8) {
        float x = sentence[s * 8 + lane];
        sincosf(2.0f * x, &myS, &myC);
    }

#define FM(Q) { Hg<Q>(ar, ai, lane); \
                float pc = __shfl_sync(FULLM, myC, Q); \
                float ps = __shfl_sync(FULLM, myS, Q); \
                PHg<Q>(ar, ai, pc, ps, lane); }
    FM(0) FM(1) FM(2) FM(3) FM(4) FM(5) FM(6) FM(7)
#undef FM

    conv_t<0, 1>(ar, ai, tc, ts, 0, lane);
    conv_t<2, 3>(ar, ai, tc, ts, 3, lane);
    conv_t<4, 5>(ar, ai, tc, ts, 6, lane);
    conv_t<6, 7>(ar, ai, tc, ts, 9, lane);
    conv_t<1, 2>(ar, ai, tc, ts, 12, lane);
    conv_t<3, 4>(ar, ai, tc, ts, 15, lane);
    conv_t<5, 6>(ar, ai, tc, ts, 18, lane);
    conv_t<7, 0>(ar, ai, tc, ts, 21, lane);
    pool_t<0, 4>(ar, ai, tc, ts, 24, lane);
    pool_t<1, 5>(ar, ai, tc, ts, 27, lane);
    pool_t<2, 6>(ar, ai, tc, ts, 30, lane);
    pool_t<3, 7>(ar, ai, tc, ts, 33, lane);
    conv_t<0, 1>(ar, ai, tc, ts, 36, lane);
    conv_t<2, 3>(ar, ai, tc, ts, 39, lane);
    conv_t<1, 2>(ar, ai, tc, ts, 42, lane);
    conv_t<3, 0>(ar, ai, tc, ts, 45, lane);
    pool_t<0, 2>(ar, ai, tc, ts, 48, lane);
    pool_t<1, 3>(ar, ai, tc, ts, 51, lane);
    conv_t<0, 1>(ar, ai, tc, ts, 54, lane);
    conv_t<1, 0>(ar, ai, tc, ts, 57, lane);
    pool_t<0, 1>(ar, ai, tc, ts, 60, lane);

    float v = 0.0f;
#pragma unroll
    for (int j = 0; j < 8; j++) v += ar[j] * ar[j] + ai[j] * ai[j];
    if ((lane >> 4) & 1) v = -v;               // Z on qubit 7 = lane bit 4
#pragma unroll
    for (int o = 16; o; o >>= 1) v += __shfl_xor_sync(FULLM, v, o);
    if (lane == 0) g_q[s] = v + QBIAS;         // single-word data+flag
}

// ============================================================
// Runtime poly fits: tanh(x) ~= x * P(x^2), Chebyshev-node Newton
// interpolation of g(v)=tanh(sqrt v)/sqrt v.
// ============================================================
__device__ __forceinline__ void fit_g8(float vmax, float* C) {   // deg-7 in v
    const float cs0 = 0.98078528f, cs1 = 0.83146961f,
                cs2 = 0.55557023f, cs3 = 0.19509032f;
    float v[8], d[8];
    v[0] = 0.5f * vmax * (1.0f + cs0);
    v[1] = 0.5f * vmax * (1.0f + cs1);
    v[2] = 0.5f * vmax * (1.0f + cs2);
    v[3] = 0.5f * vmax * (1.0f + cs3);
    v[4] = 0.5f * vmax * (1.0f - cs3);
    v[5] = 0.5f * vmax * (1.0f - cs2);
    v[6] = 0.5f * vmax * (1.0f - cs1);
    v[7] = 0.5f * vmax * (1.0f - cs0);
#pragma unroll
    for (int k = 0; k < 8; k++) {
        float x = sqrtf(v[k]);
        d[k] = tanhf(x) / x;
    }
#pragma unroll
    for (int j = 1; j < 8; j++)
#pragma unroll
        for (int k = 7; k >= 1; k--)
            if (k >= j) d[k] = (d[k] - d[k - 1]) / (v[k] - v[k - j]);
#pragma unroll
    for (int i = 0; i < 8; i++) C[i] = 0.0f;
    C[0] = d[7];
#pragma unroll
    for (int k = 6; k >= 0; k--) {
#pragma unroll
        for (int i = 7; i >= 1; i--) C[i] = C[i - 1] - v[k] * C[i];
        C[0] = d[k] - v[k] * C[0];
    }
}

__device__ __forceinline__ void fit_g6(float vmax, float* C) {   // deg-5 in v
    const float cs0 = 0.96592583f, cs1 = 0.70710678f, cs2 = 0.25881905f;
    float v[6], d[6];
    v[0] = 0.5f * vmax * (1.0f + cs0);
    v[1] = 0.5f * vmax * (1.0f + cs1);
    v[2] = 0.5f * vmax * (1.0f + cs2);
    v[3] = 0.5f * vmax * (1.0f - cs2);
    v[4] = 0.5f * vmax * (1.0f - cs1);
    v[5] = 0.5f * vmax * (1.0f - cs0);
#pragma unroll
    for (int k = 0; k < 6; k++) {
        float x = sqrtf(v[k]);
        d[k] = tanhf(x) / x;
    }
#pragma unroll
    for (int j = 1; j < 6; j++)
#pragma unroll
        for (int k = 5; k >= 1; k--)
            if (k >= j) d[k] = (d[k] - d[k - 1]) / (v[k] - v[k - j]);
#pragma unroll
    for (int i = 0; i < 6; i++) C[i] = 0.0f;
    C[0] = d[5];
#pragma unroll
    for (int k = 4; k >= 0; k--) {
#pragma unroll
        for (int i = 5; i >= 1; i--) C[i] = C[i - 1] - v[k] * C[i];
        C[0] = d[k] - v[k] * C[0];
    }
}

__device__ __forceinline__ float estrin8(const float* K, float u) {
    float u2 = u * u;
    float u4 = u2 * u2;
    float a = fmaf(K[1], u, K[0]);
    float b = fmaf(K[3], u, K[2]);
    float c = fmaf(K[5], u, K[4]);
    float d = fmaf(K[7], u, K[6]);
    float ab = fmaf(b, u2, a);
    float cd = fmaf(d, u2, c);
    return fmaf(cd, u4, ab);
}

__device__ __forceinline__ float estrin6(const float* K, float u) {
    float u2 = u * u;
    float u4 = u2 * u2;
    float a = fmaf(K[1], u, K[0]);
    float b = fmaf(K[3], u, K[2]);
    float c = fmaf(K[5], u, K[4]);
    float ab = fmaf(b, u2, a);
    return fmaf(c, u4, ab);
}

// ============================================================
// Chunked QLSTM scan, lane=gate layout (one warp per chunk).
// Lane g computes y/cos/z/act for ALL 4 wires of its gate, ONE
// shuffle gather round per step, head epilogue fused (lane=tag).
// ============================================================
__device__ void qlstm_scan(int chunk,
                           const float* __restrict__ Wf, const float* __restrict__ bf,
                           const float* __restrict__ Wi, const float* __restrict__ bi,
                           const float* __restrict__ Wu, const float* __restrict__ bu,
                           const float* __restrict__ Wo, const float* __restrict__ bo,
                           const float* __restrict__ thf, const float* __restrict__ thi,
                           const float* __restrict__ thu, const float* __restrict__ tho,
                           const float* __restrict__ Wt, const float* __restrict__ bt,
                           float* __restrict__ out, float4* hsrow) {
    const int l = threadIdx.x & 31;
    const int g = l & 3;
    const int base = l & ~3;

    const int begin = chunk * CH_LEN;
    const int warm0raw = begin - WARM;
    const int warm0 = (warm0raw < 0) ? 0 : warm0raw;
    const int end = begin + CH_LEN;

    const float* W  = (g == 0) ? Wf  : (g == 1) ? Wi  : (g == 2) ? Wu  : Wo;
    const float* b  = (g == 0) ? bf  : (g == 1) ? bi  : (g == 2) ? bu  : bo;
    const float* th = (g == 0) ? thf : (g == 1) ? thi : (g == 2) ? thu : tho;

    float w0[4], w1[4], w2[4], w3[4], w4[4], ub[4];
#pragma unroll
    for (int qq = 0; qq < 4; qq++) {
        w0[qq] = W[qq * 5 + 0];
        w1[qq] = W[qq * 5 + 1];
        w2[qq] = W[qq * 5 + 2];
        w3[qq] = W[qq * 5 + 3];
        w4[qq] = W[qq * 5 + 4];
        ub[qq] = b[qq] + th[qq];
    }

    const bool isU = (g == 2);

    float gA[6], gB[8];
    fit_g6(1.0f, gA);     // tanh on [-1,1]
    fit_g8(4.35f, gB);    // tanh on [-2.085,2.085] (|c| <= 2.071)

    float aK[6];
    {
        float s = 0.25f;
#pragma unroll
        for (int j = 0; j < 6; j++) {
            aK[j] = isU ? gA[j] : gA[j] * s;
            s *= 0.25f;
        }
    }
    const float Kc = isU ? 0.0f : 0.5f;

    // prologue: wait for first PF window
    float nq[PF];
    {
        float mn;
        do {
            mn = 1e30f;
#pragma unroll
            for (int j = 0; j < PF; j++) {
                float x = g_q[warm0 + j];
                nq[j] = x;
                mn = fminf(mn, x);
            }
        } while (mn < 5.0f);
    }

    float c0s = 0.0f, c1s = 0.0f, c2s = 0.0f, c3s = 0.0f;
    float h0 = 0.0f, h1 = 0.0f, h2 = 0.0f, h3 = 0.0f;

    for (int t0 = warm0; t0 < end; t0 += PF) {
        const bool wr = (l == 0) && (t0 >= begin);
        float pn[PF];
#pragma unroll
        for (int j = 0; j < PF; j++) pn[j] = g_q[t0 + PF + j];   // prefetch

#pragma unroll
        for (int j = 0; j < PF; j++) {
            const int t = t0 + j;
            const float qv = nq[j] - QBIAS;

            float y0 = fmaf(w2[0], h1, fmaf(w1[0], h0, fmaf(w0[0], qv, ub[0])))
                     + fmaf(w4[0], h3, w3[0] * h2);
            float y1 = fmaf(w2[1], h1, fmaf(w1[1], h0, fmaf(w0[1], qv, ub[1])))
                     + fmaf(w4[1], h3, w3[1] * h2);
            float y2 = fmaf(w2[2], h1, fmaf(w1[2], h0, fmaf(w0[2], qv, ub[2])))
                     + fmaf(w4[2], h3, w3[2] * h2);
            float y3 = fmaf(w2[3], h1, fmaf(w1[3], h0, fmaf(w0[3], qv, ub[3])))
                     + fmaf(w4[3], h3, w3[3] * h2);

            const float cz0 = __cosf(y0);
            const float cz1 = __cosf(y1);
            const float cz2 = __cosf(y2);
            const float cz3 = __cosf(y3);

            const float t23 = cz2 * cz3;
            const float z0 = cz1 * t23;
            const float z1 = cz0 * cz1;
            const float z2 = z1 * cz2;
            const float z3 = z2 * cz3;

            const float a0 = fmaf(z0, estrin6(aK, z0 * z0), Kc);
            const float a1 = fmaf(z1, estrin6(aK, z1 * z1), Kc);
            const float a2 = fmaf(z2, estrin6(aK, z2 * z2), Kc);
            const float a3 = fmaf(z3, estrin6(aK, z3 * z3), Kc);

            const float f0 = __shfl_sync(FULLM, a0, base + 0);
            const float f1 = __shfl_sync(FULLM, a1, base + 0);
            const float f2 = __shfl_sync(FULLM, a2, base + 0);
            const float f3 = __shfl_sync(FULLM, a3, base + 0);
            const float i0 = __shfl_sync(FULLM, a0, base + 1);
            const float i1 = __shfl_sync(FULLM, a1, base + 1);
            const float i2 = __shfl_sync(FULLM, a2, base + 1);
            const float i3 = __shfl_sync(FULLM, a3, base + 1);
            const float u0 = __shfl_sync(FULLM, a0, base + 2);
            const float u1 = __shfl_sync(FULLM, a1, base + 2);
            const float u2 = __shfl_sync(FULLM, a2, base + 2);
            const float u3 = __shfl_sync(FULLM, a3, base + 2);
            const float o0 = __shfl_sync(FULLM, a0, base + 3);
            const float o1 = __shfl_sync(FULLM, a1, base + 3);
            const float o2 = __shfl_sync(FULLM, a2, base + 3);
            const float o3 = __shfl_sync(FULLM, a3, base + 3);

            c0s = fmaf(f0, c0s, i0 * u0);
            c1s = fmaf(f1, c1s, i1 * u1);
            c2s = fmaf(f2, c2s, i2 * u2);
            c3s = fmaf(f3, c3s, i3 * u3);

            h0 = (o0 * c0s) * estrin8(gB, c0s * c0s);
            h1 = (o1 * c1s) * estrin8(gB, c1s * c1s);
            h2 = (o2 * c2s) * estrin8(gB, c2s * c2s);
            h3 = (o3 * c3s) * estrin8(gB, c3s * c3s);

            if (wr) hsrow[t - begin] = make_float4(h0, h1, h2, h3);
        }

        // verify prefetched window; spin only if producer behind
        float mn = pn[0];
#pragma unroll
        for (int j = 1; j < PF; j++) mn = fminf(mn, pn[j]);
        while (mn < 5.0f) {
            mn = 1e30f;
#pragma unroll
            for (int j = 0; j < PF; j++) {
                float x = g_q[t0 + PF + j];
                pn[j] = x;
                mn = fminf(mn, x);
            }
        }
#pragma unroll
        for (int j = 0; j < PF; j++) nq[j] = pn[j];
    }

    // -------- head epilogue: lane = tag, rows = this chunk --------
    __syncwarp();
    const float wt0 = Wt[l * 4 + 0];
    const float wt1 = Wt[l * 4 + 1];
    const float wt2 = Wt[l * 4 + 2];
    const float wt3 = Wt[l * 4 + 3];
    const float btv = bt[l];

    for (int r = 0; r < CH_LEN; r++) {
        float4 h = hsrow[r];
        float lg = btv;
        lg = fmaf(h.x, wt0, lg);
        lg = fmaf(h.y, wt1, lg);
        lg = fmaf(h.z, wt2, lg);
        lg = fmaf(h.w, wt3, lg);

        float m = lg;
#pragma unroll
        for (int o = 16; o; o >>= 1) m = fmaxf(m, __shfl_xor_sync(FULLM, m, o));
        float e = __expf(lg - m);
        float sum = e;
#pragma unroll
        for (int o = 16; o; o >>= 1) sum += __shfl_xor_sync(FULLM, sum, o);

        out[(begin + r) * 32 + l] = (lg - m) - __logf(sum);
    }
}

// ============================================================
// Fused kernel: 148 blocks x 512 threads. Blocks 0..15 = scan
// (4 warps = 4 chunks, threads 128..511 idle); blocks 16..147 =
// producers: 16 warps, ONE sample per warp (single sweep).
// ============================================================
__global__ void __launch_bounds__(512, 1)
fused_kernel(const float* __restrict__ sentence,
             const float* __restrict__ Wf, const float* __restrict__ bf,
             const float* __restrict__ Wi, const float* __restrict__ bi,
             const float* __restrict__ Wu, const float* __restrict__ bu,
             const float* __restrict__ Wo, const float* __restrict__ bo,
             const float* __restrict__ thf, const float* __restrict__ thi,
             const float* __restrict__ thu, const float* __restrict__ tho,
             const float* __restrict__ Wt, const float* __restrict__ bt,
             float* __restrict__ out) {
    if (blockIdx.x < NSCANBLK) {
        __shared__ float4 hbuf[4][CH_LEN];
        if (threadIdx.x < 128) {
            const int w = threadIdx.x >> 5;
            qlstm_scan(blockIdx.x * 4 + w,
                       Wf, bf, Wi, bi, Wu, bu, Wo, bo,
                       thf, thi, thu, tho, Wt, bt, out, hbuf[w]);
        }
        return;
    }

    // producer block: 16 warps, one sample each
    __shared__ float tc[63], ts[63];
    const int tid = threadIdx.x;
    if (tid < 63) { tc[tid] = g_trig[2 * tid]; ts[tid] = g_trig[2 * tid + 1]; }
    __syncthreads();

    const int lane = tid & 31;
    const int wid  = tid >> 5;
    const int s = (blockIdx.x - NSCANBLK) * 16 + wid;
    if (s < SEQN)
        qcnn_warp(sentence, s, tc, ts, lane);
}

// ============================================================
extern "C" void kernel_launch(void* const* d_in, const int* in_sizes, int n_in,
                              void* d_out, int out_size) {
    const float* sentence = (const float*)d_in[0];
    const float* qcnn_w   = (const float*)d_in[1];
    const float* Wf  = (const float*)d_in[2];
    const float* bf  = (const float*)d_in[3];
    const float* Wi  = (const float*)d_in[4];
    const float* bi  = (const float*)d_in[5];
    const float* Wu  = (const float*)d_in[6];
    const float* bu  = (const float*)d_in[7];
    const float* Wo  = (const float*)d_in[8];
    const float* bo  = (const float*)d_in[9];
    const float* thf = (const float*)d_in[10];
    const float* thi = (const float*)d_in[11];
    const float* thu = (const float*)d_in[12];
    const float* tho = (const float*)d_in[13];
    const float* Wt  = (const float*)d_in[14];
    const float* bt  = (const float*)d_in[15];
    float* out = (float*)d_out;

    prep_kernel<<<9, 256>>>(qcnn_w);
    fused_kernel<<<NBLK, 512>>>(sentence,
                                Wf, bf, Wi, bi, Wu, bu, Wo, bo,
                                thf, thi, thu, tho, Wt, bt, out);
}

// round 9
// speedup vs baseline: 30.6616x; 1.1887x over previous
#include <cuda_runtime.h>
#include <math.h>

#define SEQN 2048
#define PF 8
#define NBLK 148            // #SMs; blocks 0..15 = scan, 16..147 = producers
#define NCHUNK 64
#define CH_LEN 32           // SEQN / NCHUNK
#define WARM 40             // warm-up steps (0.731^40 ~ 3.6e-6)
#define NSCANBLK 16

#define NOT_READY -1.0e30f
#define QBIAS 10.0f
#define FULLM 0xFFFFFFFFu
#define RTC 0.70710678118654752440f

// ---- device scratch (no allocations allowed) ----
__device__ float g_trig[2 * 63];            // cos,sin of w[j]/2
__device__ volatile float g_q[SEQN + PF];   // data+flag channel: ready iff > 5

// ============================================================
// Kernel 1: trig precompute + q-channel sentinel init (+padding)
// ============================================================
__global__ void prep_kernel(const float* __restrict__ w) {
    int j = blockIdx.x * blockDim.x + threadIdx.x;
    if (blockIdx.x == 0 && threadIdx.x < 63) {
        float s, c;
        sincosf(0.5f * w[threadIdx.x], &s, &c);
        g_trig[2 * threadIdx.x]     = c;
        g_trig[2 * threadIdx.x + 1] = s;
    }
    for (int i = j; i < SEQN + PF; i += gridDim.x * blockDim.x)
        g_q[i] = (i < SEQN) ? NOT_READY : QBIAS;   // padding pre-ready
}

// ============================================================
// Warp-per-sample QCNN: 256 amplitudes, 8 per lane in registers.
// amp index = (lane << 3) | j : qubits 0-2 = j bits (in-register),
// qubits 3-7 = lane bits (shfl.xor). No __syncthreads anywhere.
//
// LIGHT-CONE REDUCTION: observable is Z on qubit 7 only. Blocks
// acting outside the backward light cone of Z_7 commute with it and
// drop EXACTLY (unitary conjugation identity). Survivors:
//   CONV1 (0,1)k0 (2,3)k3 (4,5)k6 (6,7)k9 (3,4)k15 (7,0)k21
//   POOL1 (3,7)k33
// Dropped: CONV1 (1,2),(5,6); POOL1 (0,4),(1,5),(2,6);
//          all of CONV2/POOL2/CONV3/POOL3.
// ============================================================
template<int Q>
__device__ __forceinline__ void RZg(float (&ar)[8], float (&ai)[8],
                                    float c, float s, int lane) {
#pragma unroll
    for (int j = 0; j < 8; j++) {
        int b = (Q < 3) ? ((j >> Q) & 1) : ((lane >> (Q - 3)) & 1);
        float ss = b ? s : -s;
        float nr = ar[j] * c - ai[j] * ss;
        ai[j] = fmaf(ar[j], ss, ai[j] * c);
        ar[j] = nr;
    }
}

template<int Q>
__device__ __forceinline__ void PHg(float (&ar)[8], float (&ai)[8],
                                    float c, float s, int lane) {
#pragma unroll
    for (int j = 0; j < 8; j++) {
        int b = (Q < 3) ? ((j >> Q) & 1) : ((lane >> (Q - 3)) & 1);
        float cc = b ? c : 1.0f;
        float ss = b ? s : 0.0f;
        float nr = ar[j] * cc - ai[j] * ss;
        ai[j] = fmaf(ar[j], ss, ai[j] * cc);
        ar[j] = nr;
    }
}

template<int Q>
__device__ __forceinline__ void Hg(float (&ar)[8], float (&ai)[8], int lane) {
    if (Q < 3) {
#pragma unroll
        for (int j = 0; j < 8; j++)
            if (((j >> Q) & 1) == 0) {
                int j1 = j | (1 << Q);
                float r0 = ar[j], r1 = ar[j1], i0 = ai[j], i1 = ai[j1];
                ar[j]  = (r0 + r1) * RTC;  ar[j1] = (r0 - r1) * RTC;
                ai[j]  = (i0 + i1) * RTC;  ai[j1] = (i0 - i1) * RTC;
            }
    } else {
        const int m = 1 << (Q - 3);
        float sgn = ((lane >> (Q - 3)) & 1) ? -1.0f : 1.0f;
#pragma unroll
        for (int j = 0; j < 8; j++) {
            float orr = __shfl_xor_sync(FULLM, ar[j], m);
            float oii = __shfl_xor_sync(FULLM, ai[j], m);
            ar[j] = fmaf(sgn, ar[j], orr) * RTC;
            ai[j] = fmaf(sgn, ai[j], oii) * RTC;
        }
    }
}

template<int Q>
__device__ __forceinline__ void RYg(float (&ar)[8], float (&ai)[8],
                                    float c, float s, int lane) {
    if (Q < 3) {
#pragma unroll
        for (int j = 0; j < 8; j++)
            if (((j >> Q) & 1) == 0) {
                int j1 = j | (1 << Q);
                float r0 = ar[j], r1 = ar[j1], i0 = ai[j], i1 = ai[j1];
                ar[j]  = fmaf(c, r0, -s * r1);  ar[j1] = fmaf(s, r0, c * r1);
                ai[j]  = fmaf(c, i0, -s * i1);  ai[j1] = fmaf(s, i0, c * i1);
            }
    } else {
        const int m = 1 << (Q - 3);
        float ss = ((lane >> (Q - 3)) & 1) ? s : -s;
#pragma unroll
        for (int j = 0; j < 8; j++) {
            float orr = __shfl_xor_sync(FULLM, ar[j], m);
            float oii = __shfl_xor_sync(FULLM, ai[j], m);
            ar[j] = fmaf(c, ar[j], ss * orr);
            ai[j] = fmaf(c, ai[j], ss * oii);
        }
    }
}

template<int CQ, int TQ>
__device__ __forceinline__ void CXg(float (&ar)[8], float (&ai)[8], int lane) {
    if (CQ < 3 && TQ < 3) {
#pragma unroll
        for (int j = 0; j < 8; j++)
            if ((((j >> CQ) & 1) == 1) && (((j >> TQ) & 1) == 0)) {
                int j1 = j | (1 << TQ);
                float tr = ar[j]; ar[j] = ar[j1]; ar[j1] = tr;
                float ti = ai[j]; ai[j] = ai[j1]; ai[j1] = ti;
            }
    } else if (CQ < 3) {              // target cross-lane
        const int m = 1 << (TQ - 3);
#pragma unroll
        for (int j = 0; j < 8; j++)
            if (((j >> CQ) & 1) == 1) {
                ar[j] = __shfl_xor_sync(FULLM, ar[j], m);
                ai[j] = __shfl_xor_sync(FULLM, ai[j], m);
            }
    } else if (TQ < 3) {              // control in lane, target local
        int b = (lane >> (CQ - 3)) & 1;
#pragma unroll
        for (int j = 0; j < 8; j++)
            if (((j >> TQ) & 1) == 0) {
                int j1 = j | (1 << TQ);
                float r0 = ar[j], r1 = ar[j1];
                ar[j] = b ? r1 : r0;  ar[j1] = b ? r0 : r1;
                float i0 = ai[j], i1 = ai[j1];
                ai[j] = b ? i1 : i0;  ai[j1] = b ? i0 : i1;
            }
    } else {                          // both cross-lane
        const int m = 1 << (TQ - 3);
        int b = (lane >> (CQ - 3)) & 1;
#pragma unroll
        for (int j = 0; j < 8; j++) {
            float orr = __shfl_xor_sync(FULLM, ar[j], m);
            float oii = __shfl_xor_sync(FULLM, ai[j], m);
            ar[j] = b ? orr : ar[j];
            ai[j] = b ? oii : ai[j];
        }
    }
}

template<int A, int B>
__device__ __forceinline__ void conv_t(float (&ar)[8], float (&ai)[8],
                                       const float* tc, const float* ts,
                                       int k, int lane) {
    RZg<B>(ar, ai, RTC, -RTC, lane);
    CXg<B, A>(ar, ai, lane);
    RZg<A>(ar, ai, tc[k], ts[k], lane);
    RYg<B>(ar, ai, tc[k + 1], ts[k + 1], lane);
    CXg<A, B>(ar, ai, lane);
    RYg<B>(ar, ai, tc[k + 2], ts[k + 2], lane);
    CXg<B, A>(ar, ai, lane);
    RZg<A>(ar, ai, RTC, RTC, lane);
}

template<int A, int B>
__device__ __forceinline__ void pool_t(float (&ar)[8], float (&ai)[8],
                                       const float* tc, const float* ts,
                                       int k, int lane) {
    RZg<B>(ar, ai, RTC, -RTC, lane);
    CXg<B, A>(ar, ai, lane);
    RZg<A>(ar, ai, tc[k], ts[k], lane);
    RYg<B>(ar, ai, tc[k + 1], ts[k + 1], lane);
    CXg<A, B>(ar, ai, lane);
    RYg<B>(ar, ai, tc[k + 2], ts[k + 2], lane);
}

__device__ void qcnn_warp(const float* __restrict__ sentence, int s,
                          const float* tc, const float* ts, int lane) {
    float ar[8], ai[8];
#pragma unroll
    for (int j = 0; j < 8; j++) { ar[j] = 0.0f; ai[j] = 0.0f; }
    if (lane == 0) ar[0] = 1.0f;

    float myC = 1.0f, myS = 0.0f;
    if (lane < 8) {
        float x = sentence[s * 8 + lane];
        sincosf(2.0f * x, &myS, &myC);
    }

#define FM(Q) { Hg<Q>(ar, ai, lane); \
                float pc = __shfl_sync(FULLM, myC, Q); \
                float ps = __shfl_sync(FULLM, myS, Q); \
                PHg<Q>(ar, ai, pc, ps, lane); }
    FM(0) FM(1) FM(2) FM(3) FM(4) FM(5) FM(6) FM(7)
#undef FM

    // light-cone survivors only (exact identity for <Z_7>)
    conv_t<0, 1>(ar, ai, tc, ts, 0, lane);
    conv_t<2, 3>(ar, ai, tc, ts, 3, lane);
    conv_t<4, 5>(ar, ai, tc, ts, 6, lane);
    conv_t<6, 7>(ar, ai, tc, ts, 9, lane);
    conv_t<3, 4>(ar, ai, tc, ts, 15, lane);
    conv_t<7, 0>(ar, ai, tc, ts, 21, lane);
    pool_t<3, 7>(ar, ai, tc, ts, 33, lane);

    float v = 0.0f;
#pragma unroll
    for (int j = 0; j < 8; j++) v += ar[j] * ar[j] + ai[j] * ai[j];
    if ((lane >> 4) & 1) v = -v;               // Z on qubit 7 = lane bit 4
#pragma unroll
    for (int o = 16; o; o >>= 1) v += __shfl_xor_sync(FULLM, v, o);
    if (lane == 0) g_q[s] = v + QBIAS;         // single-word data+flag
}

// ============================================================
// Runtime poly fits: tanh(x) ~= x * P(x^2), Chebyshev-node Newton
// interpolation of g(v)=tanh(sqrt v)/sqrt v.
// ============================================================
__device__ __forceinline__ void fit_g8(float vmax, float* C) {   // deg-7 in v
    const float cs0 = 0.98078528f, cs1 = 0.83146961f,
                cs2 = 0.55557023f, cs3 = 0.19509032f;
    float v[8], d[8];
    v[0] = 0.5f * vmax * (1.0f + cs0);
    v[1] = 0.5f * vmax * (1.0f + cs1);
    v[2] = 0.5f * vmax * (1.0f + cs2);
    v[3] = 0.5f * vmax * (1.0f + cs3);
    v[4] = 0.5f * vmax * (1.0f - cs3);
    v[5] = 0.5f * vmax * (1.0f - cs2);
    v[6] = 0.5f * vmax * (1.0f - cs1);
    v[7] = 0.5f * vmax * (1.0f - cs0);
#pragma unroll
    for (int k = 0; k < 8; k++) {
        float x = sqrtf(v[k]);
        d[k] = tanhf(x) / x;
    }
#pragma unroll
    for (int j = 1; j < 8; j++)
#pragma unroll
        for (int k = 7; k >= 1; k--)
            if (k >= j) d[k] = (d[k] - d[k - 1]) / (v[k] - v[k - j]);
#pragma unroll
    for (int i = 0; i < 8; i++) C[i] = 0.0f;
    C[0] = d[7];
#pragma unroll
    for (int k = 6; k >= 0; k--) {
#pragma unroll
        for (int i = 7; i >= 1; i--) C[i] = C[i - 1] - v[k] * C[i];
        C[0] = d[k] - v[k] * C[0];
    }
}

__device__ __forceinline__ void fit_g6(float vmax, float* C) {   // deg-5 in v
    const float cs0 = 0.96592583f, cs1 = 0.70710678f, cs2 = 0.25881905f;
    float v[6], d[6];
    v[0] = 0.5f * vmax * (1.0f + cs0);
    v[1] = 0.5f * vmax * (1.0f + cs1);
    v[2] = 0.5f * vmax * (1.0f + cs2);
    v[3] = 0.5f * vmax * (1.0f - cs2);
    v[4] = 0.5f * vmax * (1.0f - cs1);
    v[5] = 0.5f * vmax * (1.0f - cs0);
#pragma unroll
    for (int k = 0; k < 6; k++) {
        float x = sqrtf(v[k]);
        d[k] = tanhf(x) / x;
    }
#pragma unroll
    for (int j = 1; j < 6; j++)
#pragma unroll
        for (int k = 5; k >= 1; k--)
            if (k >= j) d[k] = (d[k] - d[k - 1]) / (v[k] - v[k - j]);
#pragma unroll
    for (int i = 0; i < 6; i++) C[i] = 0.0f;
    C[0] = d[5];
#pragma unroll
    for (int k = 4; k >= 0; k--) {
#pragma unroll
        for (int i = 5; i >= 1; i--) C[i] = C[i - 1] - v[k] * C[i];
        C[0] = d[k] - v[k] * C[0];
    }
}

__device__ __forceinline__ float estrin8(const float* K, float u) {
    float u2 = u * u;
    float u4 = u2 * u2;
    float a = fmaf(K[1], u, K[0]);
    float b = fmaf(K[3], u, K[2]);
    float c = fmaf(K[5], u, K[4]);
    float d = fmaf(K[7], u, K[6]);
    float ab = fmaf(b, u2, a);
    float cd = fmaf(d, u2, c);
    return fmaf(cd, u4, ab);
}

__device__ __forceinline__ float estrin6(const float* K, float u) {
    float u2 = u * u;
    float u4 = u2 * u2;
    float a = fmaf(K[1], u, K[0]);
    float b = fmaf(K[3], u, K[2]);
    float c = fmaf(K[5], u, K[4]);
    float ab = fmaf(b, u2, a);
    return fmaf(c, u4, ab);
}

// ============================================================
// Chunked QLSTM scan, lane=gate layout (one warp per chunk).
// ============================================================
__device__ void qlstm_scan(int chunk,
                           const float* __restrict__ Wf, const float* __restrict__ bf,
                           const float* __restrict__ Wi, const float* __restrict__ bi,
                           const float* __restrict__ Wu, const float* __restrict__ bu,
                           const float* __restrict__ Wo, const float* __restrict__ bo,
                           const float* __restrict__ thf, const float* __restrict__ thi,
                           const float* __restrict__ thu, const float* __restrict__ tho,
                           const float* __restrict__ Wt, const float* __restrict__ bt,
                           float* __restrict__ out, float4* hsrow) {
    const int l = threadIdx.x & 31;
    const int g = l & 3;
    const int base = l & ~3;

    const int begin = chunk * CH_LEN;
    const int warm0raw = begin - WARM;
    const int warm0 = (warm0raw < 0) ? 0 : warm0raw;
    const int end = begin + CH_LEN;

    const float* W  = (g == 0) ? Wf  : (g == 1) ? Wi  : (g == 2) ? Wu  : Wo;
    const float* b  = (g == 0) ? bf  : (g == 1) ? bi  : (g == 2) ? bu  : bo;
    const float* th = (g == 0) ? thf : (g == 1) ? thi : (g == 2) ? thu : tho;

    float w0[4], w1[4], w2[4], w3[4], w4[4], ub[4];
#pragma unroll
    for (int qq = 0; qq < 4; qq++) {
        w0[qq] = W[qq * 5 + 0];
        w1[qq] = W[qq * 5 + 1];
        w2[qq] = W[qq * 5 + 2];
        w3[qq] = W[qq * 5 + 3];
        w4[qq] = W[qq * 5 + 4];
        ub[qq] = b[qq] + th[qq];
    }

    const bool isU = (g == 2);

    float gA[6], gB[8];
    fit_g6(1.0f, gA);     // tanh on [-1,1]
    fit_g8(4.35f, gB);    // tanh on [-2.085,2.085] (|c| <= 2.071)

    float aK[6];
    {
        float s = 0.25f;
#pragma unroll
        for (int j = 0; j < 6; j++) {
            aK[j] = isU ? gA[j] : gA[j] * s;
            s *= 0.25f;
        }
    }
    const float Kc = isU ? 0.0f : 0.5f;

    // prologue: wait for first PF window
    float nq[PF];
    {
        float mn;
        do {
            mn = 1e30f;
#pragma unroll
            for (int j = 0; j < PF; j++) {
                float x = g_q[warm0 + j];
                nq[j] = x;
                mn = fminf(mn, x);
            }
        } while (mn < 5.0f);
    }

    float c0s = 0.0f, c1s = 0.0f, c2s = 0.0f, c3s = 0.0f;
    float h0 = 0.0f, h1 = 0.0f, h2 = 0.0f, h3 = 0.0f;

    for (int t0 = warm0; t0 < end; t0 += PF) {
        const bool wr = (l == 0) && (t0 >= begin);
        float pn[PF];
#pragma unroll
        for (int j = 0; j < PF; j++) pn[j] = g_q[t0 + PF + j];   // prefetch

#pragma unroll
        for (int j = 0; j < PF; j++) {
            const int t = t0 + j;
            const float qv = nq[j] - QBIAS;

            float y0 = fmaf(w2[0], h1, fmaf(w1[0], h0, fmaf(w0[0], qv, ub[0])))
                     + fmaf(w4[0], h3, w3[0] * h2);
            float y1 = fmaf(w2[1], h1, fmaf(w1[1], h0, fmaf(w0[1], qv, ub[1])))
                     + fmaf(w4[1], h3, w3[1] * h2);
            float y2 = fmaf(w2[2], h1, fmaf(w1[2], h0, fmaf(w0[2], qv, ub[2])))
                     + fmaf(w4[2], h3, w3[2] * h2);
            float y3 = fmaf(w2[3], h1, fmaf(w1[3], h0, fmaf(w0[3], qv, ub[3])))
                     + fmaf(w4[3], h3, w3[3] * h2);

            const float cz0 = __cosf(y0);
            const float cz1 = __cosf(y1);
            const float cz2 = __cosf(y2);
            const float cz3 = __cosf(y3);

            const float t23 = cz2 * cz3;
            const float z0 = cz1 * t23;
            const float z1 = cz0 * cz1;
            const float z2 = z1 * cz2;
            const float z3 = z2 * cz3;

            const float a0 = fmaf(z0, estrin6(aK, z0 * z0), Kc);
            const float a1 = fmaf(z1, estrin6(aK, z1 * z1), Kc);
            const float a2 = fmaf(z2, estrin6(aK, z2 * z2), Kc);
            const float a3 = fmaf(z3, estrin6(aK, z3 * z3), Kc);

            const float f0 = __shfl_sync(FULLM, a0, base + 0);
            const float f1 = __shfl_sync(FULLM, a1, base + 0);
            const float f2 = __shfl_sync(FULLM, a2, base + 0);
            const float f3 = __shfl_sync(FULLM, a3, base + 0);
            const float i0 = __shfl_sync(FULLM, a0, base + 1);
            const float i1 = __shfl_sync(FULLM, a1, base + 1);
            const float i2 = __shfl_sync(FULLM, a2, base + 1);
            const float i3 = __shfl_sync(FULLM, a3, base + 1);
            const float u0 = __shfl_sync(FULLM, a0, base + 2);
            const float u1 = __shfl_sync(FULLM, a1, base + 2);
            const float u2 = __shfl_sync(FULLM, a2, base + 2);
            const float u3 = __shfl_sync(FULLM, a3, base + 2);
            const float o0 = __shfl_sync(FULLM, a0, base + 3);
            const float o1 = __shfl_sync(FULLM, a1, base + 3);
            const float o2 = __shfl_sync(FULLM, a2, base + 3);
            const float o3 = __shfl_sync(FULLM, a3, base + 3);

            c0s = fmaf(f0, c0s, i0 * u0);
            c1s = fmaf(f1, c1s, i1 * u1);
            c2s = fmaf(f2, c2s, i2 * u2);
            c3s = fmaf(f3, c3s, i3 * u3);

            h0 = (o0 * c0s) * estrin8(gB, c0s * c0s);
            h1 = (o1 * c1s) * estrin8(gB, c1s * c1s);
            h2 = (o2 * c2s) * estrin8(gB, c2s * c2s);
            h3 = (o3 * c3s) * estrin8(gB, c3s * c3s);

            if (wr) hsrow[t - begin] = make_float4(h0, h1, h2, h3);
        }

        // verify prefetched window; spin only if producer behind
        float mn = pn[0];
#pragma unroll
        for (int j = 1; j < PF; j++) mn = fminf(mn, pn[j]);
        while (mn < 5.0f) {
            mn = 1e30f;
#pragma unroll
            for (int j = 0; j < PF; j++) {
                float x = g_q[t0 + PF + j];
                pn[j] = x;
                mn = fminf(mn, x);
            }
        }
#pragma unroll
        for (int j = 0; j < PF; j++) nq[j] = pn[j];
    }

    // -------- head epilogue: lane = tag, rows = this chunk --------
    __syncwarp();
    const float wt0 = Wt[l * 4 + 0];
    const float wt1 = Wt[l * 4 + 1];
    const float wt2 = Wt[l * 4 + 2];
    const float wt3 = Wt[l * 4 + 3];
    const float btv = bt[l];

    for (int r = 0; r < CH_LEN; r++) {
        float4 h = hsrow[r];
        float lg = btv;
        lg = fmaf(h.x, wt0, lg);
        lg = fmaf(h.y, wt1, lg);
        lg = fmaf(h.z, wt2, lg);
        lg = fmaf(h.w, wt3, lg);

        float m = lg;
#pragma unroll
        for (int o = 16; o; o >>= 1) m = fmaxf(m, __shfl_xor_sync(FULLM, m, o));
        float e = __expf(lg - m);
        float sum = e;
#pragma unroll
        for (int o = 16; o; o >>= 1) sum += __shfl_xor_sync(FULLM, sum, o);

        out[(begin + r) * 32 + l] = (lg - m) - __logf(sum);
    }
}

// ============================================================
// Fused kernel: 148 blocks x 512 threads. Blocks 0..15 = scan
// (4 warps = 4 chunks); blocks 16..147 = producers: 16 warps,
// ONE sample per warp (single sweep).
// ============================================================
__global__ void __launch_bounds__(512, 1)
fused_kernel(const float* __restrict__ sentence,
             const float* __restrict__ Wf, const float* __restrict__ bf,
             const float* __restrict__ Wi, const float* __restrict__ bi,
             const float* __restrict__ Wu, const float* __restrict__ bu,
             const float* __restrict__ Wo, const float* __restrict__ bo,
             const float* __restrict__ thf, const float* __restrict__ thi,
             const float* __restrict__ thu, const float* __restrict__ tho,
             const float* __restrict__ Wt, const float* __restrict__ bt,
             float* __restrict__ out) {
    if (blockIdx.x < NSCANBLK) {
        __shared__ float4 hbuf[4][CH_LEN];
        if (threadIdx.x < 128) {
            const int w = threadIdx.x >> 5;
            qlstm_scan(blockIdx.x * 4 + w,
                       Wf, bf, Wi, bi, Wu, bu, Wo, bo,
                       thf, thi, thu, tho, Wt, bt, out, hbuf[w]);
        }
        return;
    }

    // producer block: 16 warps, one sample each
    __shared__ float tc[63], ts[63];
    const int tid = threadIdx.x;
    if (tid < 63) { tc[tid] = g_trig[2 * tid]; ts[tid] = g_trig[2 * tid + 1]; }
    __syncthreads();

    const int lane = tid & 31;
    const int wid  = tid >> 5;
    const int s = (blockIdx.x - NSCANBLK) * 16 + wid;
    if (s < SEQN)
        qcnn_warp(sentence, s, tc, ts, lane);
}

// ============================================================
extern "C" void kernel_launch(void* const* d_in, const int* in_sizes, int n_in,
                              void* d_out, int out_size) {
    const float* sentence = (const float*)d_in[0];
    const float* qcnn_w   = (const float*)d_in[1];
    const float* Wf  = (const float*)d_in[2];
    const float* bf  = (const float*)d_in[3];
    const float* Wi  = (const float*)d_in[4];
    const float* bi  = (const float*)d_in[5];
    const float* Wu  = (const float*)d_in[6];
    const float* bu  = (const float*)d_in[7];
    const float* Wo  = (const float*)d_in[8];
    const float* bo  = (const float*)d_in[9];
    const float* thf = (const float*)d_in[10];
    const float* thi = (const float*)d_in[11];
    const float* thu = (const float*)d_in[12];
    const float* tho = (const float*)d_in[13];
    const float* Wt  = (const float*)d_in[14];
    const float* bt  = (const float*)d_in[15];
    float* out = (float*)d_out;

    prep_kernel<<<9, 256>>>(qcnn_w);
    fused_kernel<<<NBLK, 512>>>(sentence,
                                Wf, bf, Wi, bi, Wu, bu, Wo, bo,
                                thf, thi, thu, tho, Wt, bt, out);
}

// round 10
// speedup vs baseline: 49.3378x; 1.6091x over previous
#include <cuda_runtime.h>
#include <math.h>

#define SEQN 2048
#define PF 8
#define NBLK 148
#define CH_LEN 8
#define NCHUNK 256          // SEQN / CH_LEN
#define WARM 32             // 0.731^32 ~ 4e-5 truncation
#define NSCANBLK 64         // blocks 0..63: 4 warps = 4 chunks each
#define NPRODBLK 64         // blocks 64..127: warp 0 = 32 samples (sample/thread)

#define NOT_READY -1.0e30f
#define QBIAS 10.0f
#define FULLM 0xFFFFFFFFu
#define RTC 0.70710678118654752440f

// ---- device scratch (no allocations allowed) ----
__device__ float g_trig[2 * 63];            // cos,sin of w[j]/2
__device__ float g_T[16];                   // pool(3,7) transfer tensor
__device__ volatile float g_q[SEQN + PF];   // data+flag channel: ready iff > 5

// ---- complex helpers (prep only) ----
__device__ __forceinline__ float2 cmulf(float2 a, float2 b) {
    return make_float2(a.x * b.x - a.y * b.y, a.x * b.y + a.y * b.x);
}
__device__ __forceinline__ float2 cmuljf(float2 a, float2 b) {  // a * conj(b)
    return make_float2(a.x * b.x + a.y * b.y, a.y * b.x - a.x * b.y);
}
__device__ __forceinline__ float2 sigel(int m, int r, int c) {  // I,X,Y,Z entries
    if (m == 0) return make_float2(r == c ? 1.f : 0.f, 0.f);
    if (m == 1) return make_float2(r != c ? 1.f : 0.f, 0.f);
    if (m == 2) return make_float2(0.f, (r == 0 && c == 1) ? -1.f : ((r == 1 && c == 0) ? 1.f : 0.f));
    return make_float2(r == c ? (r == 0 ? 1.f : -1.f) : 0.f, 0.f);
}

// ============================================================
// Kernel 1: trig precompute + sentinel init + pool transfer tensor T.
// T[mu][nu] = Tr[ U_pool (sig_mu on q3 ⊗ sig_nu on q7) U_pool^† (Z on q7) ]
// local 2-qubit index i = 2*b7 + b3. One thread per (mu,nu).
// ============================================================
__global__ void prep_kernel(const float* __restrict__ w) {
    int j = blockIdx.x * blockDim.x + threadIdx.x;
    if (blockIdx.x == 0) {
        int t = threadIdx.x;
        if (t < 63) {
            float s, c;
            sincosf(0.5f * w[t], &s, &c);
            g_trig[2 * t] = c;
            g_trig[2 * t + 1] = s;
        } else if (t >= 64 && t < 80) {
            int idx = t - 64, mu = idx >> 2, nu = idx & 3;
            float c0, s0, c1, s1, c2, s2;
            sincosf(0.5f * w[33], &s0, &c0);   // pool(3,7) params k=33..35
            sincosf(0.5f * w[34], &s1, &c1);
            sincosf(0.5f * w[35], &s2, &c2);
            // build U column-by-column: RZ_b(-pi/2), CNOT(b,a), RZ_a(p0),
            // RY_b(p1), CNOT(a,b), RY_b(p2); a=q3=bit0, b=q7=bit1
            float2 U[4][4];
            for (int col = 0; col < 4; col++) {
                float2 u[4];
                for (int i = 0; i < 4; i++) u[i] = make_float2(i == col ? 1.f : 0.f, 0.f);
                for (int i = 0; i < 4; i++) {                    // RZ bit1 (-pi/2)
                    float ss = ((i >> 1) & 1) ? -RTC : RTC;
                    u[i] = cmulf(u[i], make_float2(RTC, ss));
                }
                { float2 tt = u[2]; u[2] = u[3]; u[3] = tt; }     // CNOT c=bit1 t=bit0
                for (int i = 0; i < 4; i++) {                    // RZ bit0 (p0)
                    float ss = (i & 1) ? s0 : -s0;
                    u[i] = cmulf(u[i], make_float2(c0, ss));
                }
                for (int i = 0; i < 2; i++) {                    // RY bit1 (p1)
                    float2 a0 = u[i], a1 = u[i + 2];
                    u[i]     = make_float2(c1 * a0.x - s1 * a1.x, c1 * a0.y - s1 * a1.y);
                    u[i + 2] = make_float2(s1 * a0.x + c1 * a1.x, s1 * a0.y + c1 * a1.y);
                }
                { float2 tt = u[1]; u[1] = u[3]; u[3] = tt; }     // CNOT c=bit0 t=bit1
                for (int i = 0; i < 2; i++) {                    // RY bit1 (p2)
                    float2 a0 = u[i], a1 = u[i + 2];
                    u[i]     = make_float2(c2 * a0.x - s2 * a1.x, c2 * a0.y - s2 * a1.y);
                    u[i + 2] = make_float2(s2 * a0.x + c2 * a1.x, s2 * a0.y + c2 * a1.y);
                }
                for (int i = 0; i < 4; i++) U[i][col] = u[i];
            }
            float2 A[4][4], Bm[4][4];
            for (int i = 0; i < 4; i++)
                for (int k = 0; k < 4; k++)
                    A[i][k] = cmulf(sigel(mu, i & 1, k & 1), sigel(nu, (i >> 1) & 1, (k >> 1) & 1));
            for (int i = 0; i < 4; i++)
                for (int k = 0; k < 4; k++) {
                    float2 acc = make_float2(0.f, 0.f);
                    for (int m = 0; m < 4; m++) {
                        float2 p = cmulf(U[i][m], A[m][k]);
                        acc.x += p.x; acc.y += p.y;
                    }
                    Bm[i][k] = acc;
                }
            float tr = 0.f;
            for (int i = 0; i < 4; i++) {
                float2 cc = make_float2(0.f, 0.f);
                for (int k = 0; k < 4; k++) {
                    float2 p = cmuljf(Bm[i][k], U[i][k]);
                    cc.x += p.x; cc.y += p.y;
                }
                tr += (i < 2) ? cc.x : -cc.x;
            }
            g_T[mu * 4 + nu] = tr;
        }
    }
    for (int i = j; i < SEQN + PF; i += gridDim.x * blockDim.x)
        g_q[i] = (i < SEQN) ? NOT_READY : QBIAS;
}

// ============================================================
// Single-thread 4-qubit (16-amp) gate machinery. All indices
// compile-time => CNOT is pure register renaming (zero cost).
// ============================================================
template<int B>
__device__ __forceinline__ void rz16(float (&ar)[16], float (&ai)[16], float c, float s) {
#pragma unroll
    for (int i = 0; i < 16; i++) {
        float ss = ((i >> B) & 1) ? s : -s;
        float nr = ar[i] * c - ai[i] * ss;
        ai[i] = fmaf(ar[i], ss, ai[i] * c);
        ar[i] = nr;
    }
}
template<int B>
__device__ __forceinline__ void ry16(float (&ar)[16], float (&ai)[16], float c, float s) {
#pragma unroll
    for (int i = 0; i < 16; i++)
        if (((i >> B) & 1) == 0) {
            int j = i | (1 << B);
            float r0 = ar[i], r1 = ar[j], i0 = ai[i], i1 = ai[j];
            ar[i] = fmaf(c, r0, -s * r1);  ar[j] = fmaf(s, r0, c * r1);
            ai[i] = fmaf(c, i0, -s * i1);  ai[j] = fmaf(s, i0, c * i1);
        }
}
template<int C, int T>
__device__ __forceinline__ void cx16(float (&ar)[16], float (&ai)[16]) {
#pragma unroll
    for (int i = 0; i < 16; i++)
        if ((((i >> C) & 1) == 1) && (((i >> T) & 1) == 0)) {
            int j = i | (1 << T);
            float t;
            t = ar[i]; ar[i] = ar[j]; ar[j] = t;
            t = ai[i]; ai[i] = ai[j]; ai[j] = t;
        }
}
template<int A, int B>
__device__ __forceinline__ void conv16(float (&ar)[16], float (&ai)[16], int k) {
    float c0 = g_trig[2 * k],     s0 = g_trig[2 * k + 1];
    float c1 = g_trig[2 * k + 2], s1 = g_trig[2 * k + 3];
    float c2 = g_trig[2 * k + 4], s2 = g_trig[2 * k + 5];
    rz16<B>(ar, ai, RTC, -RTC);
    cx16<B, A>(ar, ai);
    rz16<A>(ar, ai, c0, s0);
    ry16<B>(ar, ai, c1, s1);
    cx16<A, B>(ar, ai);
    ry16<B>(ar, ai, c2, s2);
    cx16<B, A>(ar, ai);
    rz16<A>(ar, ai, RTC, RTC);
}

// init: product state amp(b) = prod_{bk=1} (ec_k + i es_k)  (norm^2 = 16)
__device__ __forceinline__ void init16(float (&ar)[16], float (&ai)[16],
                                       const float* ec, const float* es) {
    ar[0] = 1.f; ai[0] = 0.f;
    ar[1] = ec[0]; ai[1] = es[0];
#pragma unroll
    for (int i = 0; i < 2; i++) {
        ar[2 + i] = ar[i] * ec[1] - ai[i] * es[1];
        ai[2 + i] = fmaf(ar[i], es[1], ai[i] * ec[1]);
    }
#pragma unroll
    for (int i = 0; i < 4; i++) {
        ar[4 + i] = ar[i] * ec[2] - ai[i] * es[2];
        ai[4 + i] = fmaf(ar[i], es[2], ai[i] * ec[2]);
    }
#pragma unroll
    for (int i = 0; i < 8; i++) {
        ar[8 + i] = ar[i] * ec[3] - ai[i] * es[3];
        ai[8 + i] = fmaf(ar[i], es[3], ai[i] * ec[3]);
    }
}

// Bloch vector of qubit at local bit B (amps unnormalized, norm^2=16):
// r = (1, 2Re rho01, -2Im rho01, rho00-rho11)
template<int B>
__device__ __forceinline__ void rho16(const float (&ar)[16], const float (&ai)[16], float r[4]) {
    float pr = 0.f, pi = 0.f, z = 0.f;
#pragma unroll
    for (int i = 0; i < 16; i++)
        if (((i >> B) & 1) == 0) {
            int j = i | (1 << B);
            pr = fmaf(ar[i], ar[j], fmaf(ai[i], ai[j], pr));
            pi = fmaf(ai[i], ar[j], fmaf(-ar[i], ai[j], pi));
            z  = fmaf(ar[i], ar[i], fmaf(ai[i], ai[i], z));
            z  = fmaf(-ar[j], ar[j], fmaf(-ai[j], ai[j], z));
        }
    r[0] = 1.0f;
    r[1] = 0.125f * pr;
    r[2] = -0.125f * pi;
    r[3] = 0.0625f * z;
}

// ============================================================
// Sample-per-thread QCNN: two independent 4-qubit group sims
// (exact group factorization of the light-cone-reduced circuit),
// then <Z7> = 0.25 * r3^T T r7.
//   Group A {2,3,4,5}->(b0..b3): conv(b0,b1)k3, conv(b2,b3)k6, conv(b1,b2)k15; q3=b1
//   Group B {0,1,6,7}->(b0..b3): conv(b0,b1)k0, conv(b2,b3)k9, conv(b3,b0)k21; q7=b3
// ============================================================
__device__ void qcnn_thread(const float* __restrict__ sentence, int s) {
    const float4 xa = *(const float4*)(sentence + s * 8);
    const float4 xb = *(const float4*)(sentence + s * 8 + 4);
    float x[8] = {xa.x, xa.y, xa.z, xa.w, xb.x, xb.y, xb.z, xb.w};
    float ec[8], es[8];
#pragma unroll
    for (int q = 0; q < 8; q++) __sincosf(2.0f * x[q], &es[q], &ec[q]);

    float ar[16], ai[16];
    float r3[4], r7[4];
    {
        float pc[4] = {ec[2], ec[3], ec[4], ec[5]};
        float ps[4] = {es[2], es[3], es[4], es[5]};
        init16(ar, ai, pc, ps);
        conv16<0, 1>(ar, ai, 3);
        conv16<2, 3>(ar, ai, 6);
        conv16<1, 2>(ar, ai, 15);
        rho16<1>(ar, ai, r3);
    }
    {
        float pc[4] = {ec[0], ec[1], ec[6], ec[7]};
        float ps[4] = {es[0], es[1], es[6], es[7]};
        init16(ar, ai, pc, ps);
        conv16<0, 1>(ar, ai, 0);
        conv16<2, 3>(ar, ai, 9);
        conv16<3, 0>(ar, ai, 21);
        rho16<3>(ar, ai, r7);
    }
    float acc = 0.f;
#pragma unroll
    for (int m = 0; m < 4; m++)
#pragma unroll
        for (int n = 0; n < 4; n++)
            acc = fmaf(g_T[m * 4 + n], r3[m] * r7[n], acc);

    g_q[s] = fmaf(0.25f, acc, QBIAS);   // single-word data+flag
}

// ============================================================
// Runtime poly fits + Estrin evaluators (scan activations)
// ============================================================
__device__ __forceinline__ void fit_g8(float vmax, float* C) {
    const float cs0 = 0.98078528f, cs1 = 0.83146961f,
                cs2 = 0.55557023f, cs3 = 0.19509032f;
    float v[8], d[8];
    v[0] = 0.5f * vmax * (1.0f + cs0);
    v[1] = 0.5f * vmax * (1.0f + cs1);
    v[2] = 0.5f * vmax * (1.0f + cs2);
    v[3] = 0.5f * vmax * (1.0f + cs3);
    v[4] = 0.5f * vmax * (1.0f - cs3);
    v[5] = 0.5f * vmax * (1.0f - cs2);
    v[6] = 0.5f * vmax * (1.0f - cs1);
    v[7] = 0.5f * vmax * (1.0f - cs0);
#pragma unroll
    for (int k = 0; k < 8; k++) {
        float x = sqrtf(v[k]);
        d[k] = tanhf(x) / x;
    }
#pragma unroll
    for (int j = 1; j < 8; j++)
#pragma unroll
        for (int k = 7; k >= 1; k--)
            if (k >= j) d[k] = (d[k] - d[k - 1]) / (v[k] - v[k - j]);
#pragma unroll
    for (int i = 0; i < 8; i++) C[i] = 0.0f;
    C[0] = d[7];
#pragma unroll
    for (int k = 6; k >= 0; k--) {
#pragma unroll
        for (int i = 7; i >= 1; i--) C[i] = C[i - 1] - v[k] * C[i];
        C[0] = d[k] - v[k] * C[0];
    }
}

__device__ __forceinline__ void fit_g6(float vmax, float* C) {
    const float cs0 = 0.96592583f, cs1 = 0.70710678f, cs2 = 0.25881905f;
    float v[6], d[6];
    v[0] = 0.5f * vmax * (1.0f + cs0);
    v[1] = 0.5f * vmax * (1.0f + cs1);
    v[2] = 0.5f * vmax * (1.0f + cs2);
    v[3] = 0.5f * vmax * (1.0f - cs2);
    v[4] = 0.5f * vmax * (1.0f - cs1);
    v[5] = 0.5f * vmax * (1.0f - cs0);
#pragma unroll
    for (int k = 0; k < 6; k++) {
        float x = sqrtf(v[k]);
        d[k] = tanhf(x) / x;
    }
#pragma unroll
    for (int j = 1; j < 6; j++)
#pragma unroll
        for (int k = 5; k >= 1; k--)
            if (k >= j) d[k] = (d[k] - d[k - 1]) / (v[k] - v[k - j]);
#pragma unroll
    for (int i = 0; i < 6; i++) C[i] = 0.0f;
    C[0] = d[5];
#pragma unroll
    for (int k = 4; k >= 0; k--) {
#pragma unroll
        for (int i = 5; i >= 1; i--) C[i] = C[i - 1] - v[k] * C[i];
        C[0] = d[k] - v[k] * C[0];
    }
}

__device__ __forceinline__ float estrin8(const float* K, float u) {
    float u2 = u * u;
    float u4 = u2 * u2;
    float a = fmaf(K[1], u, K[0]);
    float b = fmaf(K[3], u, K[2]);
    float c = fmaf(K[5], u, K[4]);
    float d = fmaf(K[7], u, K[6]);
    float ab = fmaf(b, u2, a);
    float cd = fmaf(d, u2, c);
    return fmaf(cd, u4, ab);
}

__device__ __forceinline__ float estrin6(const float* K, float u) {
    float u2 = u * u;
    float u4 = u2 * u2;
    float a = fmaf(K[1], u, K[0]);
    float b = fmaf(K[3], u, K[2]);
    float c = fmaf(K[5], u, K[4]);
    float ab = fmaf(b, u2, a);
    return fmaf(c, u4, ab);
}

// ============================================================
// Chunked QLSTM scan, lane=gate layout (one warp per chunk).
// ============================================================
__device__ void qlstm_scan(int chunk,
                           const float* __restrict__ Wf, const float* __restrict__ bf,
                           const float* __restrict__ Wi, const float* __restrict__ bi,
                           const float* __restrict__ Wu, const float* __restrict__ bu,
                           const float* __restrict__ Wo, const float* __restrict__ bo,
                           const float* __restrict__ thf, const float* __restrict__ thi,
                           const float* __restrict__ thu, const float* __restrict__ tho,
                           const float* __restrict__ Wt, const float* __restrict__ bt,
                           float* __restrict__ out, float4* hsrow) {
    const int l = threadIdx.x & 31;
    const int g = l & 3;
    const int base = l & ~3;

    const int begin = chunk * CH_LEN;
    const int warm0raw = begin - WARM;
    const int warm0 = (warm0raw < 0) ? 0 : warm0raw;
    const int end = begin + CH_LEN;

    const float* W  = (g == 0) ? Wf  : (g == 1) ? Wi  : (g == 2) ? Wu  : Wo;
    const float* b  = (g == 0) ? bf  : (g == 1) ? bi  : (g == 2) ? bu  : bo;
    const float* th = (g == 0) ? thf : (g == 1) ? thi : (g == 2) ? thu : tho;

    float w0[4], w1[4], w2[4], w3[4], w4[4], ub[4];
#pragma unroll
    for (int qq = 0; qq < 4; qq++) {
        w0[qq] = W[qq * 5 + 0];
        w1[qq] = W[qq * 5 + 1];
        w2[qq] = W[qq * 5 + 2];
        w3[qq] = W[qq * 5 + 3];
        w4[qq] = W[qq * 5 + 4];
        ub[qq] = b[qq] + th[qq];
    }

    const bool isU = (g == 2);

    float gA[6], gB[8];
    fit_g6(1.0f, gA);     // tanh on [-1,1]
    fit_g8(4.35f, gB);    // tanh on [-2.085,2.085] (|c| <= 2.071)

    float aK[6];
    {
        float s = 0.25f;
#pragma unroll
        for (int j = 0; j < 6; j++) {
            aK[j] = isU ? gA[j] : gA[j] * s;
            s *= 0.25f;
        }
    }
    const float Kc = isU ? 0.0f : 0.5f;

    // prologue: wait for first PF window
    float nq[PF];
    {
        float mn;
        do {
            mn = 1e30f;
#pragma unroll
            for (int j = 0; j < PF; j++) {
                float x = g_q[warm0 + j];
                nq[j] = x;
                mn = fminf(mn, x);
            }
        } while (mn < 5.0f);
    }

    float c0s = 0.0f, c1s = 0.0f, c2s = 0.0f, c3s = 0.0f;
    float h0 = 0.0f, h1 = 0.0f, h2 = 0.0f, h3 = 0.0f;

    for (int t0 = warm0; t0 < end; t0 += PF) {
        const bool wr = (l == 0) && (t0 >= begin);
        float pn[PF];
#pragma unroll
        for (int j = 0; j < PF; j++) pn[j] = g_q[t0 + PF + j];   // prefetch

#pragma unroll
        for (int j = 0; j < PF; j++) {
            const int t = t0 + j;
            const float qv = nq[j] - QBIAS;

            float y0 = fmaf(w2[0], h1, fmaf(w1[0], h0, fmaf(w0[0], qv, ub[0])))
                     + fmaf(w4[0], h3, w3[0] * h2);
            float y1 = fmaf(w2[1], h1, fmaf(w1[1], h0, fmaf(w0[1], qv, ub[1])))
                     + fmaf(w4[1], h3, w3[1] * h2);
            float y2 = fmaf(w2[2], h1, fmaf(w1[2], h0, fmaf(w0[2], qv, ub[2])))
                     + fmaf(w4[2], h3, w3[2] * h2);
            float y3 = fmaf(w2[3], h1, fmaf(w1[3], h0, fmaf(w0[3], qv, ub[3])))
                     + fmaf(w4[3], h3, w3[3] * h2);

            const float cz0 = __cosf(y0);
            const float cz1 = __cosf(y1);
            const float cz2 = __cosf(y2);
            const float cz3 = __cosf(y3);

            const float t23 = cz2 * cz3;
            const float z0 = cz1 * t23;
            const float z1 = cz0 * cz1;
            const float z2 = z1 * cz2;
            const float z3 = z2 * cz3;

            const float a0 = fmaf(z0, estrin6(aK, z0 * z0), Kc);
            const float a1 = fmaf(z1, estrin6(aK, z1 * z1), Kc);
            const float a2 = fmaf(z2, estrin6(aK, z2 * z2), Kc);
            const float a3 = fmaf(z3, estrin6(aK, z3 * z3), Kc);

            const float f0 = __shfl_sync(FULLM, a0, base + 0);
            const float f1 = __shfl_sync(FULLM, a1, base + 0);
            const float f2 = __shfl_sync(FULLM, a2, base + 0);
            const float f3 = __shfl_sync(FULLM, a3, base + 0);
            const float i0 = __shfl_sync(FULLM, a0, base + 1);
            const float i1 = __shfl_sync(FULLM, a1, base + 1);
            const float i2 = __shfl_sync(FULLM, a2, base + 1);
            const float i3 = __shfl_sync(FULLM, a3, base + 1);
            const float u0 = __shfl_sync(FULLM, a0, base + 2);
            const float u1 = __shfl_sync(FULLM, a1, base + 2);
            const float u2 = __shfl_sync(FULLM, a2, base + 2);
            const float u3 = __shfl_sync(FULLM, a3, base + 2);
            const float o0 = __shfl_sync(FULLM, a0, base + 3);
            const float o1 = __shfl_sync(FULLM, a1, base + 3);
            const float o2 = __shfl_sync(FULLM, a2, base + 3);
            const float o3 = __shfl_sync(FULLM, a3, base + 3);

            c0s = fmaf(f0, c0s, i0 * u0);
            c1s = fmaf(f1, c1s, i1 * u1);
            c2s = fmaf(f2, c2s, i2 * u2);
            c3s = fmaf(f3, c3s, i3 * u3);

            h0 = (o0 * c0s) * estrin8(gB, c0s * c0s);
            h1 = (o1 * c1s) * estrin8(gB, c1s * c1s);
            h2 = (o2 * c2s) * estrin8(gB, c2s * c2s);
            h3 = (o3 * c3s) * estrin8(gB, c3s * c3s);

            if (wr) hsrow[t - begin] = make_float4(h0, h1, h2, h3);
        }

        // verify prefetched window; spin only if producer behind
        float mn = pn[0];
#pragma unroll
        for (int j = 1; j < PF; j++) mn = fminf(mn, pn[j]);
        while (mn < 5.0f) {
            mn = 1e30f;
#pragma unroll
            for (int j = 0; j < PF; j++) {
                float x = g_q[t0 + PF + j];
                pn[j] = x;
                mn = fminf(mn, x);
            }
        }
#pragma unroll
        for (int j = 0; j < PF; j++) nq[j] = pn[j];
    }

    // -------- head epilogue: lane = tag, rows = this chunk --------
    __syncwarp();
    const float wt0 = Wt[l * 4 + 0];
    const float wt1 = Wt[l * 4 + 1];
    const float wt2 = Wt[l * 4 + 2];
    const float wt3 = Wt[l * 4 + 3];
    const float btv = bt[l];

#pragma unroll
    for (int r = 0; r < CH_LEN; r++) {
        float4 h = hsrow[r];
        float lg = btv;
        lg = fmaf(h.x, wt0, lg);
        lg = fmaf(h.y, wt1, lg);
        lg = fmaf(h.z, wt2, lg);
        lg = fmaf(h.w, wt3, lg);

        float m = lg;
#pragma unroll
        for (int o = 16; o; o >>= 1) m = fmaxf(m, __shfl_xor_sync(FULLM, m, o));
        float e = __expf(lg - m);
        float sum = e;
#pragma unroll
        for (int o = 16; o; o >>= 1) sum += __shfl_xor_sync(FULLM, sum, o);

        out[(begin + r) * 32 + l] = (lg - m) - __logf(sum);
    }
}

// ============================================================
// Fused kernel: blocks 0..63 = scan (4 warps = 4 chunks each);
// blocks 64..127 = producers (warp 0, sample per thread);
// blocks 128..147 idle.
// ============================================================
__global__ void __launch_bounds__(512, 1)
fused_kernel(const float* __restrict__ sentence,
             const float* __restrict__ Wf, const float* __restrict__ bf,
             const float* __restrict__ Wi, const float* __restrict__ bi,
             const float* __restrict__ Wu, const float* __restrict__ bu,
             const float* __restrict__ Wo, const float* __restrict__ bo,
             const float* __restrict__ thf, const float* __restrict__ thi,
             const float* __restrict__ thu, const float* __restrict__ tho,
             const float* __restrict__ Wt, const float* __restrict__ bt,
             float* __restrict__ out) {
    if (blockIdx.x < NSCANBLK) {
        __shared__ float4 hbuf[4][CH_LEN];
        if (threadIdx.x < 128) {
            const int w = threadIdx.x >> 5;
            qlstm_scan(blockIdx.x * 4 + w,
                       Wf, bf, Wi, bi, Wu, bu, Wo, bo,
                       thf, thi, thu, tho, Wt, bt, out, hbuf[w]);
        }
        return;
    }
    const int pb = blockIdx.x - NSCANBLK;
    if (pb < NPRODBLK && threadIdx.x < 32)
        qcnn_thread(sentence, pb * 32 + threadIdx.x);
}

// ============================================================
extern "C" void kernel_launch(void* const* d_in, const int* in_sizes, int n_in,
                              void* d_out, int out_size) {
    const float* sentence = (const float*)d_in[0];
    const float* qcnn_w   = (const float*)d_in[1];
    const float* Wf  = (const float*)d_in[2];
    const float* bf  = (const float*)d_in[3];
    const float* Wi  = (const float*)d_in[4];
    const float* bi  = (const float*)d_in[5];
    const float* Wu  = (const float*)d_in[6];
    const float* bu  = (const float*)d_in[7];
    const float* Wo  = (const float*)d_in[8];
    const float* bo  = (const float*)d_in[9];
    const float* thf = (const float*)d_in[10];
    const float* thi = (const float*)d_in[11];
    const float* thu = (const float*)d_in[12];
    const float* tho = (const float*)d_in[13];
    const float* Wt  = (const float*)d_in[14];
    const float* bt  = (const float*)d_in[15];
    float* out = (float*)d_out;

    prep_kernel<<<9, 256>>>(qcnn_w);
    fused_kernel<<<NBLK, 512>>>(sentence,
                                Wf, bf, Wi, bi, Wu, bu, Wo, bo,
                                thf, thi, thu, tho, Wt, bt, out);
}